// round 8
// baseline (speedup 1.0000x reference)
#include <cuda_runtime.h>
#include <cuda_bf16.h>
#include <cstdint>

#define D_MODEL 128
#define D_INNER 256
#define D_STATE 16
#define DT_RANK 8
#define N_LAYERS 4
#define LQ      1024
#define BATCH   64
#define M_TOT   (BATCH * LQ)   /* 65536 rows */
#define NCH     8              /* scan chunks */

// ---------------- static scratch (no allocation allowed) ----------------
__device__ __align__(256) float g_h  [(size_t)M_TOT * D_MODEL];        // fp32 h (head input, last layer)
__device__ __align__(256) float g_xz [(size_t)M_TOT * 2 * D_INNER];    // (u_raw | z)
__device__ __align__(256) float g_u  [(size_t)M_TOT * D_INNER];        // u fp32
__device__ __align__(256) float g_dbl[(size_t)M_TOT * 40];             // dt|B|C
__device__ __align__(256) float g_pq [(size_t)BATCH * NCH * 32 * D_INNER];
__device__ __align__(256) float g_hs [(size_t)BATCH * NCH * 16 * D_INNER];
__device__ __align__(256) __nv_bfloat16 g_hh[(size_t)M_TOT * D_MODEL];
__device__ __align__(256) __nv_bfloat16 g_hl[(size_t)M_TOT * D_MODEL];
__device__ __align__(256) __nv_bfloat16 g_uh[(size_t)M_TOT * D_INNER]; // u split, then y split (in-place)
__device__ __align__(256) __nv_bfloat16 g_ul[(size_t)M_TOT * D_INNER];
__device__ __align__(256) __nv_bfloat16 g_winh[N_LAYERS * 512 * 128];
__device__ __align__(256) __nv_bfloat16 g_winl[N_LAYERS * 512 * 128];
__device__ __align__(256) __nv_bfloat16 g_wxh [N_LAYERS * 40 * 256];
__device__ __align__(256) __nv_bfloat16 g_wxl [N_LAYERS * 40 * 256];
__device__ __align__(256) __nv_bfloat16 g_woh [N_LAYERS * 128 * 256];
__device__ __align__(256) __nv_bfloat16 g_wol [N_LAYERS * 128 * 256];

// ---------------- PTX helpers ----------------
__device__ __forceinline__ uint32_t smem_u32(const void* p) {
    uint32_t a;
    asm("{ .reg .u64 t; cvta.to.shared.u64 t, %1; cvt.u32.u64 %0, t; }" : "=r"(a) : "l"(p));
    return a;
}
__device__ __forceinline__ void cp_async16(uint32_t saddr, const void* gmem) {
    asm volatile("cp.async.ca.shared.global [%0], [%1], 16;\n" :: "r"(saddr), "l"(gmem));
}
__device__ __forceinline__ void cp_async16z(uint32_t saddr, const void* gmem, int sz) {
    asm volatile("cp.async.ca.shared.global [%0], [%1], 16, %2;\n" :: "r"(saddr), "l"(gmem), "r"(sz));
}
#define CP_COMMIT()  asm volatile("cp.async.commit_group;\n" ::)
#define CP_WAIT(n)   asm volatile("cp.async.wait_group %0;\n" :: "n"(n) : "memory")

__device__ __forceinline__ void ldsm4(uint32_t* r, uint32_t addr) {
    asm volatile("ldmatrix.sync.aligned.m8n8.x4.shared.b16 {%0,%1,%2,%3}, [%4];"
        : "=r"(r[0]), "=r"(r[1]), "=r"(r[2]), "=r"(r[3]) : "r"(addr));
}
__device__ __forceinline__ void mma16816(float* c, const uint32_t* a, const uint32_t* b) {
    asm volatile("mma.sync.aligned.m16n8k16.row.col.f32.bf16.bf16.f32 "
        "{%0,%1,%2,%3}, {%4,%5,%6,%7}, {%8,%9}, {%0,%1,%2,%3};"
        : "+f"(c[0]), "+f"(c[1]), "+f"(c[2]), "+f"(c[3])
        : "r"(a[0]), "r"(a[1]), "r"(a[2]), "r"(a[3]), "r"(b[0]), "r"(b[1]));
}

// ---------------- fp32 -> bf16 hi/lo split ----------------
__device__ __forceinline__ void split2(float v, __nv_bfloat16& h, __nv_bfloat16& l) {
    h = __float2bfloat16(v);
    l = __float2bfloat16(v - __bfloat162float(h));
}

// one launch splits all three weight tensors
__global__ __launch_bounds__(256) void split_all_kernel(
    const float* __restrict__ Win, const float* __restrict__ Wx,
    const float* __restrict__ Wo,
    __nv_bfloat16* __restrict__ winh, __nv_bfloat16* __restrict__ winl,
    __nv_bfloat16* __restrict__ wxh,  __nv_bfloat16* __restrict__ wxl,
    __nv_bfloat16* __restrict__ woh,  __nv_bfloat16* __restrict__ wol)
{
    const int nWin = N_LAYERS * 512 * 128;
    const int nWx  = N_LAYERS * 40 * 256;
    const int nWo  = N_LAYERS * 128 * 256;
    const int total = nWin + nWx + nWo;
    for (int i = blockIdx.x * 256 + threadIdx.x; i < total; i += gridDim.x * 256) {
        const float* s; __nv_bfloat16 *dh, *dl; int j;
        if (i < nWin)            { s = Win; dh = winh; dl = winl; j = i; }
        else if (i < nWin + nWx) { s = Wx;  dh = wxh;  dl = wxl;  j = i - nWin; }
        else                     { s = Wo;  dh = woh;  dl = wol;  j = i - nWin - nWx; }
        __nv_bfloat16 h, l; split2(s[j], h, l);
        dh[j] = h; dl[j] = l;
    }
}

// ---------------- embed ----------------
__global__ __launch_bounds__(256) void embed_kernel(
    const float* __restrict__ x, const float* __restrict__ Wp,
    const float* __restrict__ bp, __nv_bfloat16* __restrict__ hh,
    __nv_bfloat16* __restrict__ hl)
{
    const int total = M_TOT * (D_MODEL / 4);
    for (int i = blockIdx.x * 256 + threadIdx.x; i < total; i += gridDim.x * 256) {
        int m = i >> 5, dq = (i & 31) << 2;
        float xv = x[m];
        size_t o = (size_t)m * D_MODEL + dq;
        __nv_bfloat16 h0, l0, h1, l1, h2, l2, h3, l3;
        split2(fmaf(xv, Wp[dq + 0], bp[dq + 0]), h0, l0);
        split2(fmaf(xv, Wp[dq + 1], bp[dq + 1]), h1, l1);
        split2(fmaf(xv, Wp[dq + 2], bp[dq + 2]), h2, l2);
        split2(fmaf(xv, Wp[dq + 3], bp[dq + 3]), h3, l3);
        *(__nv_bfloat162*)(hh + o)     = __nv_bfloat162(h0, h1);
        *(__nv_bfloat162*)(hh + o + 2) = __nv_bfloat162(h2, h3);
        *(__nv_bfloat162*)(hl + o)     = __nv_bfloat162(l0, l1);
        *(__nv_bfloat162*)(hl + o + 2) = __nv_bfloat162(l2, l3);
    }
}

// ================= split-bf16 GEMM via mma.sync (HMMA) =================
// Unpadded 64B rows + XOR swizzle: 16B group cg stored at slot cg ^ ((r>>1)&3).
// All SMEM addresses r*64 + slot*16 are 16B-aligned; ldmatrix 8-lane phases
// hit 8 distinct 16B banks ({0,64,16,80,32,96,48,112} mod 128). Stage 24576B,
// 2 stages = 49152B -> 4 CTAs/SM.
#define ST_AH 0
#define ST_AL 8192
#define ST_BH 16384
#define ST_BL 20480
#define ST_STRIDE 24576
#define GEMM_SMEM 49152

__device__ __forceinline__ uint32_t swz_off(int r, int cg) {
    return (uint32_t)(r * 64 + ((cg ^ ((r >> 1) & 3)) << 4));
}

template <bool SPLIT, bool WF32>
__global__ __launch_bounds__(256, 4) void mma_gemm(
    const __nv_bfloat16* __restrict__ Ahi, const __nv_bfloat16* __restrict__ Alo,
    const __nv_bfloat16* __restrict__ Bhi, const __nv_bfloat16* __restrict__ Blo,
    float* __restrict__ C, __nv_bfloat16* __restrict__ Chi,
    __nv_bfloat16* __restrict__ Clo, int N, int K, int ldc)
{
    extern __shared__ __align__(128) __nv_bfloat16 smem[];
    const int tid = threadIdx.x;
    const int lane = tid & 31, wid = tid >> 5;
    const int wm = wid >> 1, wn = wid & 1;
    const size_t m0 = (size_t)blockIdx.x * 128;
    const int n0 = blockIdx.y * 64;
    const int nValid = (N - n0) < 64 ? (N - n0) : 64;

    const __nv_bfloat16* aH = Ahi + m0 * K;
    const __nv_bfloat16* aL = Alo + m0 * K;
    const __nv_bfloat16* bH = Bhi + (size_t)n0 * K;
    const __nv_bfloat16* bL = Blo + (size_t)n0 * K;
    const uint32_t sb = smem_u32(smem);

    float acc[2][4][4];
#pragma unroll
    for (int i = 0; i < 2; i++)
#pragma unroll
        for (int j = 0; j < 4; j++)
#pragma unroll
            for (int k = 0; k < 4; k++) acc[i][j][k] = 0.f;

    auto load_stage = [&](int kc) {
        const uint32_t st = (uint32_t)(kc & 1) * ST_STRIDE;
        const int k0 = kc << 5;
#pragma unroll
        for (int j = 0; j < 6; j++) {
            int i = tid + j * 256;
            int r, c; uint32_t dofs; const __nv_bfloat16* src; int sz = 16;
            if (i < 512)        { r = i >> 2;             c = i & 3; dofs = st + ST_AH + swz_off(r, c); src = aH + (size_t)r * K + k0 + c * 8; }
            else if (i < 1024)  { int q = i - 512;  r = q >> 2; c = q & 3; dofs = st + ST_AL + swz_off(r, c); src = aL + (size_t)r * K + k0 + c * 8; }
            else if (i < 1280)  { int q = i - 1024; r = q >> 2; c = q & 3; dofs = st + ST_BH + swz_off(r, c);
                                  int rr = r < nValid ? r : 0; src = bH + (size_t)rr * K + k0 + c * 8; if (r >= nValid) sz = 0; }
            else                { int q = i - 1280; r = q >> 2; c = q & 3; dofs = st + ST_BL + swz_off(r, c);
                                  int rr = r < nValid ? r : 0; src = bL + (size_t)rr * K + k0 + c * 8; if (r >= nValid) sz = 0; }
            cp_async16z(sb + dofs, src, sz);
        }
        CP_COMMIT();
    };

    // ldmatrix addressing: row = base + (lane&15), 16B group = (lane>>4) + ks*2.
    // Swizzle index ((row>>1)&3) is invariant under +16/+32 row offsets.
    const int rl = lane & 15;
    const int sw = (rl >> 1) & 3;
    const int cgl = lane >> 4;          // 0 or 1

    auto compute_stage = [&](int kc) {
        const uint32_t st = sb + (uint32_t)(kc & 1) * ST_STRIDE;
#pragma unroll
        for (int ks = 0; ks < 2; ks++) {
            const uint32_t colb = (uint32_t)(((cgl + ks * 2) ^ sw) << 4);
            uint32_t ah[2][4], al[2][4], bh[2][4], bl[2][4];
#pragma unroll
            for (int mi = 0; mi < 2; mi++) {
                uint32_t off = (uint32_t)((wm * 32 + mi * 16 + rl) * 64) + colb;
                ldsm4(ah[mi], st + ST_AH + off);
                ldsm4(al[mi], st + ST_AL + off);
            }
#pragma unroll
            for (int ni = 0; ni < 2; ni++) {
                uint32_t off = (uint32_t)((wn * 32 + ni * 16 + rl) * 64) + colb;
                ldsm4(bh[ni], st + ST_BH + off);
                ldsm4(bl[ni], st + ST_BL + off);
            }
#pragma unroll
            for (int mi = 0; mi < 2; mi++)
#pragma unroll
                for (int n2 = 0; n2 < 2; n2++)
#pragma unroll
                    for (int s = 0; s < 2; s++) {
                        uint32_t bhF[2] = {bh[n2][s], bh[n2][s + 2]};
                        uint32_t blF[2] = {bl[n2][s], bl[n2][s + 2]};
                        float* a = acc[mi][n2 * 2 + s];
                        mma16816(a, ah[mi], bhF);
                        mma16816(a, ah[mi], blF);
                        mma16816(a, al[mi], bhF);
                    }
        }
    };

    const int nk = K >> 5;
    load_stage(0);
    for (int kc = 0; kc < nk; kc++) {
        if (kc + 1 < nk) { load_stage(kc + 1); CP_WAIT(1); }
        else             { CP_WAIT(0); }
        __syncthreads();
        compute_stage(kc);
        __syncthreads();
    }

    const int g = lane >> 2, tg = lane & 3;
#pragma unroll
    for (int mi = 0; mi < 2; mi++) {
        size_t row = m0 + (size_t)(wm * 32 + mi * 16 + g);
#pragma unroll
        for (int ni = 0; ni < 4; ni++) {
            int col = n0 + wn * 32 + ni * 8 + tg * 2;
            if (col < N) {
                float* a = acc[mi][ni];
                size_t o0 = row * (size_t)ldc + col;
                size_t o1 = (row + 8) * (size_t)ldc + col;
                if (WF32) {
                    *(float2*)(C + o0) = make_float2(a[0], a[1]);
                    *(float2*)(C + o1) = make_float2(a[2], a[3]);
                }
                if (SPLIT) {
                    __nv_bfloat16 h0, l0, h1, l1, h2, l2, h3, l3;
                    split2(a[0], h0, l0); split2(a[1], h1, l1);
                    split2(a[2], h2, l2); split2(a[3], h3, l3);
                    *(__nv_bfloat162*)(Chi + o0) = __nv_bfloat162(h0, h1);
                    *(__nv_bfloat162*)(Clo + o0) = __nv_bfloat162(l0, l1);
                    *(__nv_bfloat162*)(Chi + o1) = __nv_bfloat162(h2, h3);
                    *(__nv_bfloat162*)(Clo + o1) = __nv_bfloat162(l2, l3);
                }
            }
        }
    }
}

// ---------------- causal depthwise conv(4) + silu (+ bf16 split out) -----
#define CONV_ROWS 16
__global__ __launch_bounds__(256) void conv_silu_kernel(
    const float* __restrict__ xz, const float* __restrict__ Wconv,
    const float* __restrict__ bconv, float* __restrict__ u,
    __nv_bfloat16* __restrict__ uh, __nv_bfloat16* __restrict__ ul)
{
    const int d = threadIdx.x;
    const int m0 = blockIdx.x * CONV_ROWS;
    const int l0 = m0 & (LQ - 1);
    const float w0 = Wconv[d * 4 + 0], w1 = Wconv[d * 4 + 1];
    const float w2 = Wconv[d * 4 + 2], w3 = Wconv[d * 4 + 3];
    const float bb = bconv[d];
    const float* base = xz + (size_t)m0 * (2 * D_INNER) + d;

    float x1 = (l0 >= 3) ? base[-3 * 2 * D_INNER] : 0.f;
    float x2 = (l0 >= 2) ? base[-2 * 2 * D_INNER] : 0.f;
    float x3 = (l0 >= 1) ? base[-1 * 2 * D_INNER] : 0.f;
#pragma unroll
    for (int r = 0; r < CONV_ROWS; r++) {
        float cur = base[(size_t)r * 2 * D_INNER];
        float acc = bb;
        acc = fmaf(w0, x1, acc); acc = fmaf(w1, x2, acc);
        acc = fmaf(w2, x3, acc); acc = fmaf(w3, cur, acc);
        float sv = __fdividef(acc, 1.f + __expf(-acc));
        size_t o = (size_t)(m0 + r) * D_INNER + d;
        u[o] = sv;
        __nv_bfloat16 h, lo; split2(sv, h, lo);
        uh[o] = h; ul[o] = lo;
        x1 = x2; x2 = x3; x3 = cur;
    }
}

// ---------------- chunked selective scan ----------------
template <bool PASSC>
__global__ __launch_bounds__(128, 2) void scan_pass(
    const float* __restrict__ dbl,          // [M][40]: dt(8) | B(16) | C(16)
    const float* __restrict__ u_in,
    const float* __restrict__ xz,           // z at col 256
    const float* __restrict__ Wdt, const float* __restrict__ bdt,
    const float* __restrict__ Alog, const float* __restrict__ Dp,
    float* __restrict__ pq, const float* __restrict__ hs,
    __nv_bfloat16* __restrict__ yh, __nv_bfloat16* __restrict__ yl)
{
    __shared__ __align__(16) float sdbl[2][16 * 40];

    const int b = blockIdx.x >> 1;
    const int d = ((blockIdx.x & 1) << 7) | threadIdx.x;
    const int ch = blockIdx.y;
    const int t0 = ch << 7;

    float wdt[8];
#pragma unroll
    for (int r = 0; r < 8; r++) wdt[r] = Wdt[d * 8 + r];
    const float bdtd = bdt[d];
    const float Dpd  = Dp[d];
    float Aneg[16];
#pragma unroll
    for (int n = 0; n < 16; n++) Aneg[n] = -__expf(Alog[d * 16 + n]);
    const float a0 = Aneg[0];
    float resid[16];
#pragma unroll
    for (int n = 0; n < 16; n++) resid[n] = fmaf(-(float)(n + 1), a0, Aneg[n]);

    const float* urd  = u_in + (size_t)b * LQ * D_INNER + d;
    const float* zrd  = xz + (size_t)b * LQ * (2 * D_INNER) + D_INNER + d;
    const float* dsrc = dbl + (size_t)b * LQ * 40;
    __nv_bfloat16* yhd = yh + (size_t)b * LQ * D_INNER + d;
    __nv_bfloat16* yld = yl + (size_t)b * LQ * D_INNER + d;

    float u_pf[4], z_pf[4];
#pragma unroll
    for (int i = 0; i < 4; i++) {
        u_pf[i] = urd[(size_t)(t0 + i) * D_INNER];
        if (PASSC) z_pf[i] = zrd[(size_t)(t0 + i) * (2 * D_INNER)];
    }

    auto issue = [&](int c) {
        const float* src = dsrc + (size_t)c * 16 * 40;
        float* dst = sdbl[c & 1];
        int i = threadIdx.x;
        cp_async16(smem_u32(dst + i * 4), src + i * 4);
        if (i < 32) cp_async16(smem_u32(dst + (i + 128) * 4), src + (i + 128) * 4);
        CP_COMMIT();
    };
    const int c0 = ch << 3;
    issue(c0);
    issue(c0 + 1);

    float hst[16], Pp[16];
    if (PASSC) {
        size_t hb = ((size_t)(b * NCH + ch) * 16) * D_INNER + d;
#pragma unroll
        for (int n = 0; n < 16; n++) hst[n] = hs[hb + (size_t)n * D_INNER];
    } else {
#pragma unroll
        for (int n = 0; n < 16; n++) { hst[n] = 0.f; Pp[n] = 1.f; }
    }

    for (int ci = 0; ci < 8; ci++) {
        if (ci < 7) CP_WAIT(1); else CP_WAIT(0);
        __syncthreads();
        const float* sh = sdbl[ci & 1];
#pragma unroll
        for (int s = 0; s < 16; s++) {
            const int t = t0 + (ci << 4) + s;
            float u_t = u_pf[s & 3];
            float z_t;
            if (PASSC) z_t = z_pf[s & 3];
            int tn = t + 4;
            if (tn < LQ) {
                u_pf[s & 3] = urd[(size_t)tn * D_INNER];
                if (PASSC) z_pf[s & 3] = zrd[(size_t)tn * (2 * D_INNER)];
            }
            const float* row = sh + s * 40;
            float4 q0 = *(const float4*)(row);
            float4 q1 = *(const float4*)(row + 4);
            float xdt = bdtd;
            xdt = fmaf(q0.x, wdt[0], xdt); xdt = fmaf(q0.y, wdt[1], xdt);
            xdt = fmaf(q0.z, wdt[2], xdt); xdt = fmaf(q0.w, wdt[3], xdt);
            xdt = fmaf(q1.x, wdt[4], xdt); xdt = fmaf(q1.y, wdt[5], xdt);
            xdt = fmaf(q1.z, wdt[6], xdt); xdt = fmaf(q1.w, wdt[7], xdt);
            float delta = (xdt > 20.f) ? xdt : log1pf(__expf(xdt));
            float du = delta * u_t;

            float p = __expf(delta * a0);
            float pw[16];
            pw[0] = p;
#pragma unroll
            for (int n = 1; n < 16; n++) { int a = (n + 1) >> 1; pw[n] = pw[a - 1] * pw[n - a]; }

            float4 B0 = *(const float4*)(row + 8);
            float4 B1 = *(const float4*)(row + 12);
            float4 B2 = *(const float4*)(row + 16);
            float4 B3 = *(const float4*)(row + 20);
            float Bn[16] = {B0.x, B0.y, B0.z, B0.w, B1.x, B1.y, B1.z, B1.w,
                            B2.x, B2.y, B2.z, B2.w, B3.x, B3.y, B3.z, B3.w};
            if (PASSC) {
                float4 C0 = *(const float4*)(row + 24);
                float4 C1 = *(const float4*)(row + 28);
                float4 C2 = *(const float4*)(row + 32);
                float4 C3 = *(const float4*)(row + 36);
                float Cn[16] = {C0.x, C0.y, C0.z, C0.w, C1.x, C1.y, C1.z, C1.w,
                                C2.x, C2.y, C2.z, C2.w, C3.x, C3.y, C3.z, C3.w};
                float y0 = 0.f, y1 = 0.f;
#pragma unroll
                for (int n = 0; n < 16; n += 2) {
                    float dA0 = pw[n]     * fmaf(delta, resid[n],     1.f);
                    float dA1 = pw[n + 1] * fmaf(delta, resid[n + 1], 1.f);
                    hst[n]     = fmaf(dA0, hst[n],     du * Bn[n]);
                    hst[n + 1] = fmaf(dA1, hst[n + 1], du * Bn[n + 1]);
                    y0 = fmaf(hst[n],     Cn[n],     y0);
                    y1 = fmaf(hst[n + 1], Cn[n + 1], y1);
                }
                float sg = __fdividef(z_t, 1.f + __expf(-z_t));
                float yv = (y0 + y1 + u_t * Dpd) * sg;
                __nv_bfloat16 hh2, ll2; split2(yv, hh2, ll2);
                yhd[(size_t)t * D_INNER] = hh2;
                yld[(size_t)t * D_INNER] = ll2;
            } else {
#pragma unroll
                for (int n = 0; n < 16; n += 2) {
                    float dA0 = pw[n]     * fmaf(delta, resid[n],     1.f);
                    float dA1 = pw[n + 1] * fmaf(delta, resid[n + 1], 1.f);
                    hst[n]     = fmaf(dA0, hst[n],     du * Bn[n]);
                    hst[n + 1] = fmaf(dA1, hst[n + 1], du * Bn[n + 1]);
                    Pp[n]     *= dA0;
                    Pp[n + 1] *= dA1;
                }
            }
        }
        __syncthreads();
        if (ci + 2 < 8) issue(c0 + ci + 2);
    }

    if (!PASSC) {
        size_t pb = ((size_t)(b * NCH + ch) * 32) * D_INNER + d;
#pragma unroll
        for (int n = 0; n < 16; n++) {
            pq[pb + (size_t)n * D_INNER]        = Pp[n];
            pq[pb + (size_t)(16 + n) * D_INNER] = hst[n];
        }
    }
}

// Pass B: stitch chunk start states sequentially per (b, d) lane.
__global__ __launch_bounds__(256) void scan_stitch(
    const float* __restrict__ pq, float* __restrict__ hs)
{
    const int b = blockIdx.x, d = threadIdx.x;
    float h[16];
#pragma unroll
    for (int n = 0; n < 16; n++) h[n] = 0.f;
#pragma unroll
    for (int ch = 0; ch < NCH; ch++) {
        size_t hb = ((size_t)(b * NCH + ch) * 16) * D_INNER + d;
#pragma unroll
        for (int n = 0; n < 16; n++) hs[hb + (size_t)n * D_INNER] = h[n];
        if (ch < NCH - 1) {
            size_t pb = ((size_t)(b * NCH + ch) * 32) * D_INNER + d;
#pragma unroll
            for (int n = 0; n < 16; n++)
                h[n] = fmaf(pq[pb + (size_t)n * D_INNER], h[n],
                            pq[pb + (size_t)(16 + n) * D_INNER]);
        }
    }
}

// ---------------- mean over L + LayerNorm + classifier ----------------
__global__ __launch_bounds__(512) void head_kernel(
    const float* __restrict__ h, const float* __restrict__ g_ln,
    const float* __restrict__ b_ln, const float* __restrict__ Wc,
    const float* __restrict__ bc, float* __restrict__ out)
{
    const int b = blockIdx.x, tid = threadIdx.x;
    const int d = tid & 127, q = tid >> 7;
    __shared__ float part[4][128];
    __shared__ float red[128];
    __shared__ float mn[128];

    const float* p = h + (size_t)b * LQ * D_MODEL + (size_t)q * 256 * D_MODEL + d;
    float s = 0.f;
#pragma unroll 8
    for (int l = 0; l < 256; l++) s += p[(size_t)l * D_MODEL];
    part[q][d] = s;
    __syncthreads();

    if (tid < 128) {
        float m = (part[0][tid] + part[1][tid] + part[2][tid] + part[3][tid]) * (1.f / (float)LQ);
        red[tid] = m;
        mn[tid] = m;
    }
    __syncthreads();
    for (int off = 64; off > 0; off >>= 1) {
        if (tid < off) red[tid] += red[tid + off];
        __syncthreads();
    }
    float mu = red[0] * (1.f / 128.f);
    __syncthreads();
    if (tid < 128) { float dm = mn[tid] - mu; red[tid] = dm * dm; }
    __syncthreads();
    for (int off = 64; off > 0; off >>= 1) {
        if (tid < off) red[tid] += red[tid + off];
        __syncthreads();
    }
    float var = red[0] * (1.f / 128.f);
    float rs = rsqrtf(var + 1e-5f);
    __syncthreads();
    if (tid < 128) mn[tid] = (mn[tid] - mu) * rs * g_ln[tid] + b_ln[tid];
    __syncthreads();
    if (tid < 10) {
        float a = bc[tid];
        const float* w = Wc + tid * 128;
#pragma unroll 8
        for (int dd = 0; dd < 128; dd++) a = fmaf(mn[dd], w[dd], a);
        out[b * 10 + tid] = a;
    }
}

// ---------------- orchestration ----------------
extern "C" void kernel_launch(void* const* d_in, const int* in_sizes, int n_in,
                              void* d_out, int out_size)
{
    const float* x     = (const float*)d_in[0];
    const float* Wp    = (const float*)d_in[1];
    const float* bp    = (const float*)d_in[2];
    const float* Win   = (const float*)d_in[3];
    const float* Wconv = (const float*)d_in[4];
    const float* bconv = (const float*)d_in[5];
    const float* Wx    = (const float*)d_in[6];
    const float* Wdt   = (const float*)d_in[7];
    const float* bdt   = (const float*)d_in[8];
    const float* Alog  = (const float*)d_in[9];
    const float* Dp    = (const float*)d_in[10];
    const float* Wo    = (const float*)d_in[11];
    const float* gln   = (const float*)d_in[12];
    const float* bln   = (const float*)d_in[13];
    const float* Wc    = (const float*)d_in[14];
    const float* bc    = (const float*)d_in[15];
    float* out = (float*)d_out;

    float *h, *xzb, *ub, *dblb, *pqb, *hsb;
    __nv_bfloat16 *hh, *hl, *uh, *ul, *winh, *winl, *wxh, *wxl, *woh, *wol;
    cudaGetSymbolAddress((void**)&h,    g_h);
    cudaGetSymbolAddress((void**)&xzb,  g_xz);
    cudaGetSymbolAddress((void**)&ub,   g_u);
    cudaGetSymbolAddress((void**)&dblb, g_dbl);
    cudaGetSymbolAddress((void**)&pqb,  g_pq);
    cudaGetSymbolAddress((void**)&hsb,  g_hs);
    cudaGetSymbolAddress((void**)&hh,   g_hh);
    cudaGetSymbolAddress((void**)&hl,   g_hl);
    cudaGetSymbolAddress((void**)&uh,   g_uh);
    cudaGetSymbolAddress((void**)&ul,   g_ul);
    cudaGetSymbolAddress((void**)&winh, g_winh);
    cudaGetSymbolAddress((void**)&winl, g_winl);
    cudaGetSymbolAddress((void**)&wxh,  g_wxh);
    cudaGetSymbolAddress((void**)&wxl,  g_wxl);
    cudaGetSymbolAddress((void**)&woh,  g_woh);
    cudaGetSymbolAddress((void**)&wol,  g_wol);

    cudaFuncSetAttribute((const void*)mma_gemm<false, true>, cudaFuncAttributeMaxDynamicSharedMemorySize, GEMM_SMEM);
    cudaFuncSetAttribute((const void*)mma_gemm<true, false>, cudaFuncAttributeMaxDynamicSharedMemorySize, GEMM_SMEM);

    split_all_kernel<<<1696, 256>>>(Win, Wx, Wo, winh, winl, wxh, wxl, woh, wol);
    embed_kernel<<<2048, 256>>>(x, Wp, bp, hh, hl);

    for (int i = 0; i < N_LAYERS; i++) {
        const bool last = (i == N_LAYERS - 1);
        // xz = h @ Win^T   (M=65536, N=512, K=128)
        mma_gemm<false, true><<<dim3(M_TOT / 128, 8), 256, GEMM_SMEM>>>(
            hh, hl, winh + (size_t)i * 512 * 128, winl + (size_t)i * 512 * 128,
            xzb, nullptr, nullptr, 512, 128, 512);
        // depthwise conv + silu -> u (fp32 + bf16 split)
        conv_silu_kernel<<<M_TOT / CONV_ROWS, 256>>>(
            xzb, Wconv + (size_t)i * D_INNER * 4, bconv + (size_t)i * D_INNER, ub, uh, ul);
        // dbl = u @ Wx^T   (N=40, K=256)
        mma_gemm<false, true><<<dim3(M_TOT / 128, 1), 256, GEMM_SMEM>>>(
            uh, ul, wxh + (size_t)i * 40 * 256, wxl + (size_t)i * 40 * 256,
            dblb, nullptr, nullptr, 40, 256, 40);
        // chunked scan: pass A (chunks 0..6), stitch, pass C (all chunks)
        scan_pass<false><<<dim3(128, NCH - 1), 128>>>(
            dblb, ub, xzb,
            Wdt + (size_t)i * D_INNER * DT_RANK, bdt + (size_t)i * D_INNER,
            Alog + (size_t)i * D_INNER * D_STATE, Dp + (size_t)i * D_INNER,
            pqb, nullptr, nullptr, nullptr);
        scan_stitch<<<BATCH, 256>>>(pqb, hsb);
        scan_pass<true><<<dim3(128, NCH), 128>>>(
            dblb, ub, xzb,
            Wdt + (size_t)i * D_INNER * DT_RANK, bdt + (size_t)i * D_INNER,
            Alog + (size_t)i * D_INNER * D_STATE, Dp + (size_t)i * D_INNER,
            nullptr, hsb, uh, ul);
        // h = y @ Wo^T    (N=128, K=256)
        if (last)
            mma_gemm<false, true><<<dim3(M_TOT / 128, 2), 256, GEMM_SMEM>>>(
                uh, ul, woh + (size_t)i * 128 * 256, wol + (size_t)i * 128 * 256,
                h, nullptr, nullptr, 128, 256, 128);
        else
            mma_gemm<true, false><<<dim3(M_TOT / 128, 2), 256, GEMM_SMEM>>>(
                uh, ul, woh + (size_t)i * 128 * 256, wol + (size_t)i * 128 * 256,
                nullptr, hh, hl, 128, 256, 128);
    }

    head_kernel<<<BATCH, 512>>>(h, gln, bln, Wc, bc, out);
}

// round 9
// speedup vs baseline: 1.0909x; 1.0909x over previous
#include <cuda_runtime.h>
#include <cuda_bf16.h>
#include <cstdint>

#define D_MODEL 128
#define D_INNER 256
#define D_STATE 16
#define DT_RANK 8
#define N_LAYERS 4
#define LQ      1024
#define BATCH   64
#define M_TOT   (BATCH * LQ)   /* 65536 rows */
#define NCH     8              /* scan chunks */

// ---------------- static scratch (no allocation allowed) ----------------
__device__ __align__(256) float g_h  [(size_t)M_TOT * D_MODEL];        // fp32 h (head input, last layer)
__device__ __align__(256) float g_xz [(size_t)M_TOT * 2 * D_INNER];    // (u_raw | z)
__device__ __align__(256) float g_u  [(size_t)M_TOT * D_INNER];        // u fp32
__device__ __align__(256) float g_dbl[(size_t)M_TOT * 40];             // dt|B|C
__device__ __align__(256) float g_pq [(size_t)BATCH * NCH * 32 * D_INNER]; // P|q per chunk
__device__ __align__(256) __nv_bfloat16 g_hh[(size_t)M_TOT * D_MODEL];
__device__ __align__(256) __nv_bfloat16 g_hl[(size_t)M_TOT * D_MODEL];
__device__ __align__(256) __nv_bfloat16 g_uh[(size_t)M_TOT * D_INNER]; // u split, then y split (in-place)
__device__ __align__(256) __nv_bfloat16 g_ul[(size_t)M_TOT * D_INNER];
__device__ __align__(256) __nv_bfloat16 g_winh[N_LAYERS * 512 * 128];
__device__ __align__(256) __nv_bfloat16 g_winl[N_LAYERS * 512 * 128];
__device__ __align__(256) __nv_bfloat16 g_wxh [N_LAYERS * 40 * 256];
__device__ __align__(256) __nv_bfloat16 g_wxl [N_LAYERS * 40 * 256];
__device__ __align__(256) __nv_bfloat16 g_woh [N_LAYERS * 128 * 256];
__device__ __align__(256) __nv_bfloat16 g_wol [N_LAYERS * 128 * 256];

// ---------------- PTX helpers ----------------
__device__ __forceinline__ uint32_t smem_u32(const void* p) {
    uint32_t a;
    asm("{ .reg .u64 t; cvta.to.shared.u64 t, %1; cvt.u32.u64 %0, t; }" : "=r"(a) : "l"(p));
    return a;
}
__device__ __forceinline__ void cp_async16(uint32_t saddr, const void* gmem) {
    asm volatile("cp.async.ca.shared.global [%0], [%1], 16;\n" :: "r"(saddr), "l"(gmem));
}
__device__ __forceinline__ void cp_async16z(uint32_t saddr, const void* gmem, int sz) {
    asm volatile("cp.async.ca.shared.global [%0], [%1], 16, %2;\n" :: "r"(saddr), "l"(gmem), "r"(sz));
}
#define CP_COMMIT()  asm volatile("cp.async.commit_group;\n" ::)
#define CP_WAIT(n)   asm volatile("cp.async.wait_group %0;\n" :: "n"(n) : "memory")

__device__ __forceinline__ void ldsm4(uint32_t* r, uint32_t addr) {
    asm volatile("ldmatrix.sync.aligned.m8n8.x4.shared.b16 {%0,%1,%2,%3}, [%4];"
        : "=r"(r[0]), "=r"(r[1]), "=r"(r[2]), "=r"(r[3]) : "r"(addr));
}
__device__ __forceinline__ void mma16816(float* c, const uint32_t* a, const uint32_t* b) {
    asm volatile("mma.sync.aligned.m16n8k16.row.col.f32.bf16.bf16.f32 "
        "{%0,%1,%2,%3}, {%4,%5,%6,%7}, {%8,%9}, {%0,%1,%2,%3};"
        : "+f"(c[0]), "+f"(c[1]), "+f"(c[2]), "+f"(c[3])
        : "r"(a[0]), "r"(a[1]), "r"(a[2]), "r"(a[3]), "r"(b[0]), "r"(b[1]));
}

// ---------------- fp32 -> bf16 hi/lo split ----------------
__device__ __forceinline__ void split2(float v, __nv_bfloat16& h, __nv_bfloat16& l) {
    h = __float2bfloat16(v);
    l = __float2bfloat16(v - __bfloat162float(h));
}

// one launch splits all three weight tensors
__global__ __launch_bounds__(256) void split_all_kernel(
    const float* __restrict__ Win, const float* __restrict__ Wx,
    const float* __restrict__ Wo,
    __nv_bfloat16* __restrict__ winh, __nv_bfloat16* __restrict__ winl,
    __nv_bfloat16* __restrict__ wxh,  __nv_bfloat16* __restrict__ wxl,
    __nv_bfloat16* __restrict__ woh,  __nv_bfloat16* __restrict__ wol)
{
    const int nWin = N_LAYERS * 512 * 128;
    const int nWx  = N_LAYERS * 40 * 256;
    const int nWo  = N_LAYERS * 128 * 256;
    const int total = nWin + nWx + nWo;
    for (int i = blockIdx.x * 256 + threadIdx.x; i < total; i += gridDim.x * 256) {
        const float* s; __nv_bfloat16 *dh, *dl; int j;
        if (i < nWin)            { s = Win; dh = winh; dl = winl; j = i; }
        else if (i < nWin + nWx) { s = Wx;  dh = wxh;  dl = wxl;  j = i - nWin; }
        else                     { s = Wo;  dh = woh;  dl = wol;  j = i - nWin - nWx; }
        __nv_bfloat16 h, l; split2(s[j], h, l);
        dh[j] = h; dl[j] = l;
    }
}

// ---------------- embed ----------------
__global__ __launch_bounds__(256) void embed_kernel(
    const float* __restrict__ x, const float* __restrict__ Wp,
    const float* __restrict__ bp, __nv_bfloat16* __restrict__ hh,
    __nv_bfloat16* __restrict__ hl)
{
    const int total = M_TOT * (D_MODEL / 4);
    for (int i = blockIdx.x * 256 + threadIdx.x; i < total; i += gridDim.x * 256) {
        int m = i >> 5, dq = (i & 31) << 2;
        float xv = x[m];
        size_t o = (size_t)m * D_MODEL + dq;
        __nv_bfloat16 h0, l0, h1, l1, h2, l2, h3, l3;
        split2(fmaf(xv, Wp[dq + 0], bp[dq + 0]), h0, l0);
        split2(fmaf(xv, Wp[dq + 1], bp[dq + 1]), h1, l1);
        split2(fmaf(xv, Wp[dq + 2], bp[dq + 2]), h2, l2);
        split2(fmaf(xv, Wp[dq + 3], bp[dq + 3]), h3, l3);
        *(__nv_bfloat162*)(hh + o)     = __nv_bfloat162(h0, h1);
        *(__nv_bfloat162*)(hh + o + 2) = __nv_bfloat162(h2, h3);
        *(__nv_bfloat162*)(hl + o)     = __nv_bfloat162(l0, l1);
        *(__nv_bfloat162*)(hl + o + 2) = __nv_bfloat162(l2, l3);
    }
}

// ================= split-bf16 GEMM via mma.sync (HMMA) =================
// Round-4 proven layout: rows padded to 40 bf16 (80B), 3 CTAs/SM.
#define ST_AH 0
#define ST_AL 10240
#define ST_BH 20480
#define ST_BL 25600
#define ST_STRIDE 30720
#define GEMM_SMEM 61440

template <bool SPLIT, bool WF32, bool TAIL>
__global__ __launch_bounds__(256) void mma_gemm(
    const __nv_bfloat16* __restrict__ Ahi, const __nv_bfloat16* __restrict__ Alo,
    const __nv_bfloat16* __restrict__ Bhi, const __nv_bfloat16* __restrict__ Blo,
    float* __restrict__ C, __nv_bfloat16* __restrict__ Chi,
    __nv_bfloat16* __restrict__ Clo, int N, int K, int ldc)
{
    extern __shared__ __align__(128) __nv_bfloat16 smem[];
    const int tid = threadIdx.x;
    const int lane = tid & 31, wid = tid >> 5;
    const int wm = wid >> 1, wn = wid & 1;
    const size_t m0 = (size_t)blockIdx.x * 128;
    const int n0 = blockIdx.y * 64;
    const int nValid = TAIL ? ((N - n0) < 64 ? (N - n0) : 64) : 64;

    const __nv_bfloat16* aH = Ahi + m0 * K;
    const __nv_bfloat16* aL = Alo + m0 * K;
    const __nv_bfloat16* bH = Bhi + (size_t)n0 * K;
    const __nv_bfloat16* bL = Blo + (size_t)n0 * K;
    const uint32_t sb = smem_u32(smem);

    float acc[2][4][4];
#pragma unroll
    for (int i = 0; i < 2; i++)
#pragma unroll
        for (int j = 0; j < 4; j++)
#pragma unroll
            for (int k = 0; k < 4; k++) acc[i][j][k] = 0.f;

    auto load_stage = [&](int kc) {
        const uint32_t st = (uint32_t)(kc & 1) * ST_STRIDE;
        const int k0 = kc << 5;
#pragma unroll
        for (int j = 0; j < 6; j++) {
            int i = tid + j * 256;
            int r, c; uint32_t dofs; const __nv_bfloat16* src; int sz = 16;
            if (i < 512)        { r = i >> 2;             c = i & 3; dofs = st + ST_AH + (uint32_t)(r * 40 + c * 8) * 2; src = aH + (size_t)r * K + k0 + c * 8; }
            else if (i < 1024)  { int q = i - 512;  r = q >> 2; c = q & 3; dofs = st + ST_AL + (uint32_t)(r * 40 + c * 8) * 2; src = aL + (size_t)r * K + k0 + c * 8; }
            else if (i < 1280)  { int q = i - 1024; r = q >> 2; c = q & 3; dofs = st + ST_BH + (uint32_t)(r * 40 + c * 8) * 2;
                                  if (TAIL) { int rr = r < nValid ? r : 0; src = bH + (size_t)rr * K + k0 + c * 8; if (r >= nValid) sz = 0; }
                                  else       src = bH + (size_t)r * K + k0 + c * 8; }
            else                { int q = i - 1280; r = q >> 2; c = q & 3; dofs = st + ST_BL + (uint32_t)(r * 40 + c * 8) * 2;
                                  if (TAIL) { int rr = r < nValid ? r : 0; src = bL + (size_t)rr * K + k0 + c * 8; if (r >= nValid) sz = 0; }
                                  else       src = bL + (size_t)r * K + k0 + c * 8; }
            if (TAIL) cp_async16z(sb + dofs, src, sz);
            else      cp_async16 (sb + dofs, src);
        }
        CP_COMMIT();
    };

    const uint32_t aRow = (uint32_t)((wm * 32 + (lane & 15)) * 40 + (lane >> 4) * 8) * 2;
    const uint32_t bRow = (uint32_t)((wn * 32 + (lane & 15)) * 40 + (lane >> 4) * 8) * 2;

    auto compute_stage = [&](int kc) {
        const uint32_t st = sb + (uint32_t)(kc & 1) * ST_STRIDE;
#pragma unroll
        for (int ks = 0; ks < 2; ks++) {
            uint32_t ah[2][4], al[2][4], bh[2][4], bl[2][4];
#pragma unroll
            for (int mi = 0; mi < 2; mi++) {
                uint32_t off = aRow + (uint32_t)(mi * 16 * 40 + ks * 16) * 2;
                ldsm4(ah[mi], st + ST_AH + off);
                ldsm4(al[mi], st + ST_AL + off);
            }
#pragma unroll
            for (int ni = 0; ni < 2; ni++) {
                uint32_t off = bRow + (uint32_t)(ni * 16 * 40 + ks * 16) * 2;
                ldsm4(bh[ni], st + ST_BH + off);
                ldsm4(bl[ni], st + ST_BL + off);
            }
#pragma unroll
            for (int mi = 0; mi < 2; mi++)
#pragma unroll
                for (int n2 = 0; n2 < 2; n2++)
#pragma unroll
                    for (int s = 0; s < 2; s++) {
                        uint32_t bhF[2] = {bh[n2][s], bh[n2][s + 2]};
                        uint32_t blF[2] = {bl[n2][s], bl[n2][s + 2]};
                        float* a = acc[mi][n2 * 2 + s];
                        mma16816(a, ah[mi], bhF);
                        mma16816(a, ah[mi], blF);
                        mma16816(a, al[mi], bhF);
                    }
        }
    };

    const int nk = K >> 5;
    load_stage(0);
    for (int kc = 0; kc < nk; kc++) {
        if (kc + 1 < nk) { load_stage(kc + 1); CP_WAIT(1); }
        else             { CP_WAIT(0); }
        __syncthreads();
        compute_stage(kc);
        __syncthreads();
    }

    const int g = lane >> 2, tg = lane & 3;
#pragma unroll
    for (int mi = 0; mi < 2; mi++) {
        size_t row = m0 + (size_t)(wm * 32 + mi * 16 + g);
#pragma unroll
        for (int ni = 0; ni < 4; ni++) {
            int col = n0 + wn * 32 + ni * 8 + tg * 2;
            if (!TAIL || col < N) {
                float* a = acc[mi][ni];
                size_t o0 = row * (size_t)ldc + col;
                size_t o1 = (row + 8) * (size_t)ldc + col;
                if (WF32) {
                    *(float2*)(C + o0) = make_float2(a[0], a[1]);
                    *(float2*)(C + o1) = make_float2(a[2], a[3]);
                }
                if (SPLIT) {
                    __nv_bfloat16 h0, l0, h1, l1, h2, l2, h3, l3;
                    split2(a[0], h0, l0); split2(a[1], h1, l1);
                    split2(a[2], h2, l2); split2(a[3], h3, l3);
                    *(__nv_bfloat162*)(Chi + o0) = __nv_bfloat162(h0, h1);
                    *(__nv_bfloat162*)(Clo + o0) = __nv_bfloat162(l0, l1);
                    *(__nv_bfloat162*)(Chi + o1) = __nv_bfloat162(h2, h3);
                    *(__nv_bfloat162*)(Clo + o1) = __nv_bfloat162(l2, l3);
                }
            }
        }
    }
}

// ---------------- causal depthwise conv(4) + silu (+ bf16 split out) -----
#define CONV_ROWS 16
__global__ __launch_bounds__(256) void conv_silu_kernel(
    const float* __restrict__ xz, const float* __restrict__ Wconv,
    const float* __restrict__ bconv, float* __restrict__ u,
    __nv_bfloat16* __restrict__ uh, __nv_bfloat16* __restrict__ ul)
{
    const int d = threadIdx.x;
    const int m0 = blockIdx.x * CONV_ROWS;
    const int l0 = m0 & (LQ - 1);
    const float w0 = Wconv[d * 4 + 0], w1 = Wconv[d * 4 + 1];
    const float w2 = Wconv[d * 4 + 2], w3 = Wconv[d * 4 + 3];
    const float bb = bconv[d];
    const float* base = xz + (size_t)m0 * (2 * D_INNER) + d;

    float x1 = (l0 >= 3) ? base[-3 * 2 * D_INNER] : 0.f;
    float x2 = (l0 >= 2) ? base[-2 * 2 * D_INNER] : 0.f;
    float x3 = (l0 >= 1) ? base[-1 * 2 * D_INNER] : 0.f;
#pragma unroll
    for (int r = 0; r < CONV_ROWS; r++) {
        float cur = base[(size_t)r * 2 * D_INNER];
        float acc = bb;
        acc = fmaf(w0, x1, acc); acc = fmaf(w1, x2, acc);
        acc = fmaf(w2, x3, acc); acc = fmaf(w3, cur, acc);
        float sv = __fdividef(acc, 1.f + __expf(-acc));
        size_t o = (size_t)(m0 + r) * D_INNER + d;
        u[o] = sv;
        __nv_bfloat16 h, lo; split2(sv, h, lo);
        uh[o] = h; ul[o] = lo;
        x1 = x2; x2 = x3; x3 = cur;
    }
}

// ---------------- chunked selective scan ----------------
// Pass A (PASSC=false): per chunk compute q=scan-from-zero; P via delta-sum
//                       telescope (P_n = exp(sum_delta * A_n)).
// Pass C (PASSC=true):  fold own prefix from pq (chunks 0..ch-1), rescan
//                       chunk, emit y (gated) in place over uh/ul.
template <bool PASSC>
__global__ __launch_bounds__(128, 2) void scan_pass(
    const float* __restrict__ dbl,          // [M][40]: dt(8) | B(16) | C(16)
    const float* __restrict__ u_in,
    const float* __restrict__ xz,           // z at col 256
    const float* __restrict__ Wdt, const float* __restrict__ bdt,
    const float* __restrict__ Alog, const float* __restrict__ Dp,
    float* __restrict__ pq_out, const float* __restrict__ pq_in,
    __nv_bfloat16* __restrict__ yh, __nv_bfloat16* __restrict__ yl)
{
    __shared__ __align__(16) float sdbl[2][16 * 40];

    const int b = blockIdx.x >> 1;
    const int d = ((blockIdx.x & 1) << 7) | threadIdx.x;
    const int ch = blockIdx.y;
    const int t0 = ch << 7;

    float wdt[8];
#pragma unroll
    for (int r = 0; r < 8; r++) wdt[r] = Wdt[d * 8 + r];
    const float bdtd = bdt[d];
    const float Dpd  = Dp[d];
    float Aneg[16];
#pragma unroll
    for (int n = 0; n < 16; n++) Aneg[n] = -__expf(Alog[d * 16 + n]);
    const float a0 = Aneg[0];
    float resid[16];
#pragma unroll
    for (int n = 0; n < 16; n++) resid[n] = fmaf(-(float)(n + 1), a0, Aneg[n]);

    const float* urd  = u_in + (size_t)b * LQ * D_INNER + d;
    const float* zrd  = xz + (size_t)b * LQ * (2 * D_INNER) + D_INNER + d;
    const float* dsrc = dbl + (size_t)b * LQ * 40;
    __nv_bfloat16* yhd = yh + (size_t)b * LQ * D_INNER + d;
    __nv_bfloat16* yld = yl + (size_t)b * LQ * D_INNER + d;

    float u_pf[4], z_pf[4];
#pragma unroll
    for (int i = 0; i < 4; i++) {
        u_pf[i] = urd[(size_t)(t0 + i) * D_INNER];
        if (PASSC) z_pf[i] = zrd[(size_t)(t0 + i) * (2 * D_INNER)];
    }

    auto issue = [&](int c) {
        const float* src = dsrc + (size_t)c * 16 * 40;
        float* dst = sdbl[c & 1];
        int i = threadIdx.x;
        cp_async16(smem_u32(dst + i * 4), src + i * 4);
        if (i < 32) cp_async16(smem_u32(dst + (i + 128) * 4), src + (i + 128) * 4);
        CP_COMMIT();
    };
    const int c0 = ch << 3;
    issue(c0);
    issue(c0 + 1);

    float hst[16];
#pragma unroll
    for (int n = 0; n < 16; n++) hst[n] = 0.f;
    float dsum = 0.f;

    if (PASSC) {
        // fold prefix chunks 0..ch-1: h = P*h + q  (overlaps with cp.async)
        for (int cc = 0; cc < ch; cc++) {
            size_t pb = ((size_t)(b * NCH + cc) * 32) * D_INNER + d;
#pragma unroll
            for (int n = 0; n < 16; n++)
                hst[n] = fmaf(pq_in[pb + (size_t)n * D_INNER], hst[n],
                              pq_in[pb + (size_t)(16 + n) * D_INNER]);
        }
    }

    for (int ci = 0; ci < 8; ci++) {
        if (ci < 7) CP_WAIT(1); else CP_WAIT(0);
        __syncthreads();
        const float* sh = sdbl[ci & 1];
#pragma unroll
        for (int s = 0; s < 16; s++) {
            const int t = t0 + (ci << 4) + s;
            float u_t = u_pf[s & 3];
            float z_t;
            if (PASSC) z_t = z_pf[s & 3];
            int tn = t + 4;
            if (tn < LQ) {
                u_pf[s & 3] = urd[(size_t)tn * D_INNER];
                if (PASSC) z_pf[s & 3] = zrd[(size_t)tn * (2 * D_INNER)];
            }
            const float* row = sh + s * 40;
            float4 q0 = *(const float4*)(row);
            float4 q1 = *(const float4*)(row + 4);
            float xdt = bdtd;
            xdt = fmaf(q0.x, wdt[0], xdt); xdt = fmaf(q0.y, wdt[1], xdt);
            xdt = fmaf(q0.z, wdt[2], xdt); xdt = fmaf(q0.w, wdt[3], xdt);
            xdt = fmaf(q1.x, wdt[4], xdt); xdt = fmaf(q1.y, wdt[5], xdt);
            xdt = fmaf(q1.z, wdt[6], xdt); xdt = fmaf(q1.w, wdt[7], xdt);
            float delta = (xdt > 20.f) ? xdt : log1pf(__expf(xdt));
            float du = delta * u_t;

            float p = __expf(delta * a0);
            float pw[16];
            pw[0] = p;
#pragma unroll
            for (int n = 1; n < 16; n++) { int a = (n + 1) >> 1; pw[n] = pw[a - 1] * pw[n - a]; }

            float4 B0 = *(const float4*)(row + 8);
            float4 B1 = *(const float4*)(row + 12);
            float4 B2 = *(const float4*)(row + 16);
            float4 B3 = *(const float4*)(row + 20);
            float Bn[16] = {B0.x, B0.y, B0.z, B0.w, B1.x, B1.y, B1.z, B1.w,
                            B2.x, B2.y, B2.z, B2.w, B3.x, B3.y, B3.z, B3.w};
            if (PASSC) {
                float4 C0 = *(const float4*)(row + 24);
                float4 C1 = *(const float4*)(row + 28);
                float4 C2 = *(const float4*)(row + 32);
                float4 C3 = *(const float4*)(row + 36);
                float Cn[16] = {C0.x, C0.y, C0.z, C0.w, C1.x, C1.y, C1.z, C1.w,
                                C2.x, C2.y, C2.z, C2.w, C3.x, C3.y, C3.z, C3.w};
                float y0 = 0.f, y1 = 0.f;
#pragma unroll
                for (int n = 0; n < 16; n += 2) {
                    float dA0 = pw[n]     * fmaf(delta, resid[n],     1.f);
                    float dA1 = pw[n + 1] * fmaf(delta, resid[n + 1], 1.f);
                    hst[n]     = fmaf(dA0, hst[n],     du * Bn[n]);
                    hst[n + 1] = fmaf(dA1, hst[n + 1], du * Bn[n + 1]);
                    y0 = fmaf(hst[n],     Cn[n],     y0);
                    y1 = fmaf(hst[n + 1], Cn[n + 1], y1);
                }
                float sg = __fdividef(z_t, 1.f + __expf(-z_t));
                float yv = (y0 + y1 + u_t * Dpd) * sg;
                __nv_bfloat16 hh2, ll2; split2(yv, hh2, ll2);
                yhd[(size_t)t * D_INNER] = hh2;
                yld[(size_t)t * D_INNER] = ll2;
            } else {
#pragma unroll
                for (int n = 0; n < 16; n += 2) {
                    float dA0 = pw[n]     * fmaf(delta, resid[n],     1.f);
                    float dA1 = pw[n + 1] * fmaf(delta, resid[n + 1], 1.f);
                    hst[n]     = fmaf(dA0, hst[n],     du * Bn[n]);
                    hst[n + 1] = fmaf(dA1, hst[n + 1], du * Bn[n + 1]);
                }
                dsum += delta;
            }
        }
        __syncthreads();
        if (ci + 2 < 8) issue(c0 + ci + 2);
    }

    if (!PASSC) {
        size_t pb = ((size_t)(b * NCH + ch) * 32) * D_INNER + d;
#pragma unroll
        for (int n = 0; n < 16; n++) {
            pq_out[pb + (size_t)n * D_INNER]        = __expf(dsum * Aneg[n]);
            pq_out[pb + (size_t)(16 + n) * D_INNER] = hst[n];
        }
    }
}

// ---------------- mean over L + LayerNorm + classifier ----------------
__global__ __launch_bounds__(512) void head_kernel(
    const float* __restrict__ h, const float* __restrict__ g_ln,
    const float* __restrict__ b_ln, const float* __restrict__ Wc,
    const float* __restrict__ bc, float* __restrict__ out)
{
    const int b = blockIdx.x, tid = threadIdx.x;
    const int d = tid & 127, q = tid >> 7;
    __shared__ float part[4][128];
    __shared__ float red[128];
    __shared__ float mn[128];

    const float* p = h + (size_t)b * LQ * D_MODEL + (size_t)q * 256 * D_MODEL + d;
    float s = 0.f;
#pragma unroll 8
    for (int l = 0; l < 256; l++) s += p[(size_t)l * D_MODEL];
    part[q][d] = s;
    __syncthreads();

    if (tid < 128) {
        float m = (part[0][tid] + part[1][tid] + part[2][tid] + part[3][tid]) * (1.f / (float)LQ);
        red[tid] = m;
        mn[tid] = m;
    }
    __syncthreads();
    for (int off = 64; off > 0; off >>= 1) {
        if (tid < off) red[tid] += red[tid + off];
        __syncthreads();
    }
    float mu = red[0] * (1.f / 128.f);
    __syncthreads();
    if (tid < 128) { float dm = mn[tid] - mu; red[tid] = dm * dm; }
    __syncthreads();
    for (int off = 64; off > 0; off >>= 1) {
        if (tid < off) red[tid] += red[tid + off];
        __syncthreads();
    }
    float var = red[0] * (1.f / 128.f);
    float rs = rsqrtf(var + 1e-5f);
    __syncthreads();
    if (tid < 128) mn[tid] = (mn[tid] - mu) * rs * g_ln[tid] + b_ln[tid];
    __syncthreads();
    if (tid < 10) {
        float a = bc[tid];
        const float* w = Wc + tid * 128;
#pragma unroll 8
        for (int dd = 0; dd < 128; dd++) a = fmaf(mn[dd], w[dd], a);
        out[b * 10 + tid] = a;
    }
}

// ---------------- orchestration ----------------
extern "C" void kernel_launch(void* const* d_in, const int* in_sizes, int n_in,
                              void* d_out, int out_size)
{
    const float* x     = (const float*)d_in[0];
    const float* Wp    = (const float*)d_in[1];
    const float* bp    = (const float*)d_in[2];
    const float* Win   = (const float*)d_in[3];
    const float* Wconv = (const float*)d_in[4];
    const float* bconv = (const float*)d_in[5];
    const float* Wx    = (const float*)d_in[6];
    const float* Wdt   = (const float*)d_in[7];
    const float* bdt   = (const float*)d_in[8];
    const float* Alog  = (const float*)d_in[9];
    const float* Dp    = (const float*)d_in[10];
    const float* Wo    = (const float*)d_in[11];
    const float* gln   = (const float*)d_in[12];
    const float* bln   = (const float*)d_in[13];
    const float* Wc    = (const float*)d_in[14];
    const float* bc    = (const float*)d_in[15];
    float* out = (float*)d_out;

    float *h, *xzb, *ub, *dblb, *pqb;
    __nv_bfloat16 *hh, *hl, *uh, *ul, *winh, *winl, *wxh, *wxl, *woh, *wol;
    cudaGetSymbolAddress((void**)&h,    g_h);
    cudaGetSymbolAddress((void**)&xzb,  g_xz);
    cudaGetSymbolAddress((void**)&ub,   g_u);
    cudaGetSymbolAddress((void**)&dblb, g_dbl);
    cudaGetSymbolAddress((void**)&pqb,  g_pq);
    cudaGetSymbolAddress((void**)&hh,   g_hh);
    cudaGetSymbolAddress((void**)&hl,   g_hl);
    cudaGetSymbolAddress((void**)&uh,   g_uh);
    cudaGetSymbolAddress((void**)&ul,   g_ul);
    cudaGetSymbolAddress((void**)&winh, g_winh);
    cudaGetSymbolAddress((void**)&winl, g_winl);
    cudaGetSymbolAddress((void**)&wxh,  g_wxh);
    cudaGetSymbolAddress((void**)&wxl,  g_wxl);
    cudaGetSymbolAddress((void**)&woh,  g_woh);
    cudaGetSymbolAddress((void**)&wol,  g_wol);

    cudaFuncSetAttribute((const void*)mma_gemm<false, true, false>, cudaFuncAttributeMaxDynamicSharedMemorySize, GEMM_SMEM);
    cudaFuncSetAttribute((const void*)mma_gemm<false, true, true>,  cudaFuncAttributeMaxDynamicSharedMemorySize, GEMM_SMEM);
    cudaFuncSetAttribute((const void*)mma_gemm<true, false, false>, cudaFuncAttributeMaxDynamicSharedMemorySize, GEMM_SMEM);

    split_all_kernel<<<1696, 256>>>(Win, Wx, Wo, winh, winl, wxh, wxl, woh, wol);
    embed_kernel<<<2048, 256>>>(x, Wp, bp, hh, hl);

    for (int i = 0; i < N_LAYERS; i++) {
        const bool last = (i == N_LAYERS - 1);
        // xz = h @ Win^T   (M=65536, N=512, K=128) — full tiles
        mma_gemm<false, true, false><<<dim3(M_TOT / 128, 8), 256, GEMM_SMEM>>>(
            hh, hl, winh + (size_t)i * 512 * 128, winl + (size_t)i * 512 * 128,
            xzb, nullptr, nullptr, 512, 128, 512);
        // depthwise conv + silu -> u (fp32 + bf16 split)
        conv_silu_kernel<<<M_TOT / CONV_ROWS, 256>>>(
            xzb, Wconv + (size_t)i * D_INNER * 4, bconv + (size_t)i * D_INNER, ub, uh, ul);
        // dbl = u @ Wx^T   (N=40, K=256) — tail tile
        mma_gemm<false, true, true><<<dim3(M_TOT / 128, 1), 256, GEMM_SMEM>>>(
            uh, ul, wxh + (size_t)i * 40 * 256, wxl + (size_t)i * 40 * 256,
            dblb, nullptr, nullptr, 40, 256, 40);
        // chunked scan: pass A (chunks 0..6, q + telescoped P), pass C (fold prefix + emit y)
        scan_pass<false><<<dim3(128, NCH - 1), 128>>>(
            dblb, ub, xzb,
            Wdt + (size_t)i * D_INNER * DT_RANK, bdt + (size_t)i * D_INNER,
            Alog + (size_t)i * D_INNER * D_STATE, Dp + (size_t)i * D_INNER,
            pqb, nullptr, nullptr, nullptr);
        scan_pass<true><<<dim3(128, NCH), 128>>>(
            dblb, ub, xzb,
            Wdt + (size_t)i * D_INNER * DT_RANK, bdt + (size_t)i * D_INNER,
            Alog + (size_t)i * D_INNER * D_STATE, Dp + (size_t)i * D_INNER,
            nullptr, pqb, uh, ul);
        // h = y @ Wo^T    (N=128, K=256) — full tiles
        if (last)
            mma_gemm<false, true, false><<<dim3(M_TOT / 128, 2), 256, GEMM_SMEM>>>(
                uh, ul, woh + (size_t)i * 128 * 256, wol + (size_t)i * 128 * 256,
                h, nullptr, nullptr, 128, 256, 128);
        else
            mma_gemm<true, false, false><<<dim3(M_TOT / 128, 2), 256, GEMM_SMEM>>>(
                uh, ul, woh + (size_t)i * 128 * 256, wol + (size_t)i * 128 * 256,
                nullptr, hh, hl, 128, 256, 128);
    }

    head_kernel<<<BATCH, 512>>>(h, gln, bln, Wc, bc, out);
}

// round 10
// speedup vs baseline: 1.1175x; 1.0244x over previous
#include <cuda_runtime.h>
#include <cuda_bf16.h>
#include <cstdint>

#define D_MODEL 128
#define D_INNER 256
#define D_STATE 16
#define DT_RANK 8
#define N_LAYERS 4
#define LQ      1024
#define BATCH   64
#define M_TOT   (BATCH * LQ)   /* 65536 rows */
#define NCH     8              /* scan chunks */

// ---------------- static scratch (no allocation allowed) ----------------
__device__ __align__(256) float g_h  [(size_t)M_TOT * D_MODEL];        // fp32 h (head input, last layer)
__device__ __align__(256) float g_xz [(size_t)M_TOT * 2 * D_INNER];    // (u_raw | z)
__device__ __align__(256) float g_dbl[(size_t)M_TOT * 40];             // dt|B|C
__device__ __align__(256) float g_pq [(size_t)BATCH * NCH * 32 * D_INNER]; // P|q per chunk
__device__ __align__(256) __nv_bfloat16 g_hh[(size_t)M_TOT * D_MODEL];
__device__ __align__(256) __nv_bfloat16 g_hl[(size_t)M_TOT * D_MODEL];
__device__ __align__(256) __nv_bfloat16 g_uh[(size_t)M_TOT * D_INNER]; // u split, then y split (in-place)
__device__ __align__(256) __nv_bfloat16 g_ul[(size_t)M_TOT * D_INNER];
__device__ __align__(256) __nv_bfloat16 g_winh[N_LAYERS * 512 * 128];
__device__ __align__(256) __nv_bfloat16 g_winl[N_LAYERS * 512 * 128];
__device__ __align__(256) __nv_bfloat16 g_wxh [N_LAYERS * 40 * 256];
__device__ __align__(256) __nv_bfloat16 g_wxl [N_LAYERS * 40 * 256];
__device__ __align__(256) __nv_bfloat16 g_woh [N_LAYERS * 128 * 256];
__device__ __align__(256) __nv_bfloat16 g_wol [N_LAYERS * 128 * 256];

// ---------------- PTX helpers ----------------
__device__ __forceinline__ uint32_t smem_u32(const void* p) {
    uint32_t a;
    asm("{ .reg .u64 t; cvta.to.shared.u64 t, %1; cvt.u32.u64 %0, t; }" : "=r"(a) : "l"(p));
    return a;
}
__device__ __forceinline__ void cp_async16(uint32_t saddr, const void* gmem) {
    asm volatile("cp.async.ca.shared.global [%0], [%1], 16;\n" :: "r"(saddr), "l"(gmem));
}
__device__ __forceinline__ void cp_async16z(uint32_t saddr, const void* gmem, int sz) {
    asm volatile("cp.async.ca.shared.global [%0], [%1], 16, %2;\n" :: "r"(saddr), "l"(gmem), "r"(sz));
}
#define CP_COMMIT()  asm volatile("cp.async.commit_group;\n" ::)
#define CP_WAIT(n)   asm volatile("cp.async.wait_group %0;\n" :: "n"(n) : "memory")

__device__ __forceinline__ void ldsm4(uint32_t* r, uint32_t addr) {
    asm volatile("ldmatrix.sync.aligned.m8n8.x4.shared.b16 {%0,%1,%2,%3}, [%4];"
        : "=r"(r[0]), "=r"(r[1]), "=r"(r[2]), "=r"(r[3]) : "r"(addr));
}
__device__ __forceinline__ void mma16816(float* c, const uint32_t* a, const uint32_t* b) {
    asm volatile("mma.sync.aligned.m16n8k16.row.col.f32.bf16.bf16.f32 "
        "{%0,%1,%2,%3}, {%4,%5,%6,%7}, {%8,%9}, {%0,%1,%2,%3};"
        : "+f"(c[0]), "+f"(c[1]), "+f"(c[2]), "+f"(c[3])
        : "r"(a[0]), "r"(a[1]), "r"(a[2]), "r"(a[3]), "r"(b[0]), "r"(b[1]));
}

// ---------------- fp32 -> bf16 hi/lo split ----------------
__device__ __forceinline__ void split2(float v, __nv_bfloat16& h, __nv_bfloat16& l) {
    h = __float2bfloat16(v);
    l = __float2bfloat16(v - __bfloat162float(h));
}

// ---------------- prep: weight split + embed in one launch ----------------
// blocks [0, 8192): embed; blocks [8192, 8192+1696): weight split.
#define EMBED_BLOCKS 8192
#define SPLIT_BLOCKS 1696
__global__ __launch_bounds__(256) void prep_kernel(
    const float* __restrict__ x, const float* __restrict__ Wp,
    const float* __restrict__ bp,
    const float* __restrict__ Win, const float* __restrict__ Wx,
    const float* __restrict__ Wo,
    __nv_bfloat16* __restrict__ hh,   __nv_bfloat16* __restrict__ hl,
    __nv_bfloat16* __restrict__ winh, __nv_bfloat16* __restrict__ winl,
    __nv_bfloat16* __restrict__ wxh,  __nv_bfloat16* __restrict__ wxl,
    __nv_bfloat16* __restrict__ woh,  __nv_bfloat16* __restrict__ wol)
{
    if (blockIdx.x < EMBED_BLOCKS) {
        int i = blockIdx.x * 256 + threadIdx.x;       // one per 4 d-values
        int m = i >> 5, dq = (i & 31) << 2;
        float xv = x[m];
        size_t o = (size_t)m * D_MODEL + dq;
        __nv_bfloat16 h0, l0, h1, l1, h2, l2, h3, l3;
        split2(fmaf(xv, Wp[dq + 0], bp[dq + 0]), h0, l0);
        split2(fmaf(xv, Wp[dq + 1], bp[dq + 1]), h1, l1);
        split2(fmaf(xv, Wp[dq + 2], bp[dq + 2]), h2, l2);
        split2(fmaf(xv, Wp[dq + 3], bp[dq + 3]), h3, l3);
        *(__nv_bfloat162*)(hh + o)     = __nv_bfloat162(h0, h1);
        *(__nv_bfloat162*)(hh + o + 2) = __nv_bfloat162(h2, h3);
        *(__nv_bfloat162*)(hl + o)     = __nv_bfloat162(l0, l1);
        *(__nv_bfloat162*)(hl + o + 2) = __nv_bfloat162(l2, l3);
    } else {
        const int nWin = N_LAYERS * 512 * 128;
        const int nWx  = N_LAYERS * 40 * 256;
        const int nWo  = N_LAYERS * 128 * 256;
        const int total = nWin + nWx + nWo;            // 433152
        int i = (blockIdx.x - EMBED_BLOCKS) * 256 + threadIdx.x;
        if (i < total) {
            const float* s; __nv_bfloat16 *dh, *dl; int j;
            if (i < nWin)            { s = Win; dh = winh; dl = winl; j = i; }
            else if (i < nWin + nWx) { s = Wx;  dh = wxh;  dl = wxl;  j = i - nWin; }
            else                     { s = Wo;  dh = woh;  dl = wol;  j = i - nWin - nWx; }
            __nv_bfloat16 h, l; split2(s[j], h, l);
            dh[j] = h; dl[j] = l;
        }
    }
}

// ================= split-bf16 GEMM via mma.sync (HMMA) =================
// Round-4 proven layout: rows padded to 40 bf16 (80B), 3 CTAs/SM.
#define ST_AH 0
#define ST_AL 10240
#define ST_BH 20480
#define ST_BL 25600
#define ST_STRIDE 30720
#define GEMM_SMEM 61440

template <bool SPLIT, bool WF32, bool TAIL>
__global__ __launch_bounds__(256) void mma_gemm(
    const __nv_bfloat16* __restrict__ Ahi, const __nv_bfloat16* __restrict__ Alo,
    const __nv_bfloat16* __restrict__ Bhi, const __nv_bfloat16* __restrict__ Blo,
    float* __restrict__ C, __nv_bfloat16* __restrict__ Chi,
    __nv_bfloat16* __restrict__ Clo, int N, int K, int ldc)
{
    extern __shared__ __align__(128) __nv_bfloat16 smem[];
    const int tid = threadIdx.x;
    const int lane = tid & 31, wid = tid >> 5;
    const int wm = wid >> 1, wn = wid & 1;
    const size_t m0 = (size_t)blockIdx.x * 128;
    const int n0 = blockIdx.y * 64;
    const int nValid = TAIL ? ((N - n0) < 64 ? (N - n0) : 64) : 64;

    const __nv_bfloat16* aH = Ahi + m0 * K;
    const __nv_bfloat16* aL = Alo + m0 * K;
    const __nv_bfloat16* bH = Bhi + (size_t)n0 * K;
    const __nv_bfloat16* bL = Blo + (size_t)n0 * K;
    const uint32_t sb = smem_u32(smem);

    float acc[2][4][4];
#pragma unroll
    for (int i = 0; i < 2; i++)
#pragma unroll
        for (int j = 0; j < 4; j++)
#pragma unroll
            for (int k = 0; k < 4; k++) acc[i][j][k] = 0.f;

    auto load_stage = [&](int kc) {
        const uint32_t st = (uint32_t)(kc & 1) * ST_STRIDE;
        const int k0 = kc << 5;
#pragma unroll
        for (int j = 0; j < 6; j++) {
            int i = tid + j * 256;
            int r, c; uint32_t dofs; const __nv_bfloat16* src; int sz = 16;
            if (i < 512)        { r = i >> 2;             c = i & 3; dofs = st + ST_AH + (uint32_t)(r * 40 + c * 8) * 2; src = aH + (size_t)r * K + k0 + c * 8; }
            else if (i < 1024)  { int q = i - 512;  r = q >> 2; c = q & 3; dofs = st + ST_AL + (uint32_t)(r * 40 + c * 8) * 2; src = aL + (size_t)r * K + k0 + c * 8; }
            else if (i < 1280)  { int q = i - 1024; r = q >> 2; c = q & 3; dofs = st + ST_BH + (uint32_t)(r * 40 + c * 8) * 2;
                                  if (TAIL) { int rr = r < nValid ? r : 0; src = bH + (size_t)rr * K + k0 + c * 8; if (r >= nValid) sz = 0; }
                                  else       src = bH + (size_t)r * K + k0 + c * 8; }
            else                { int q = i - 1280; r = q >> 2; c = q & 3; dofs = st + ST_BL + (uint32_t)(r * 40 + c * 8) * 2;
                                  if (TAIL) { int rr = r < nValid ? r : 0; src = bL + (size_t)rr * K + k0 + c * 8; if (r >= nValid) sz = 0; }
                                  else       src = bL + (size_t)r * K + k0 + c * 8; }
            if (TAIL) cp_async16z(sb + dofs, src, sz);
            else      cp_async16 (sb + dofs, src);
        }
        CP_COMMIT();
    };

    const uint32_t aRow = (uint32_t)((wm * 32 + (lane & 15)) * 40 + (lane >> 4) * 8) * 2;
    const uint32_t bRow = (uint32_t)((wn * 32 + (lane & 15)) * 40 + (lane >> 4) * 8) * 2;

    auto compute_stage = [&](int kc) {
        const uint32_t st = sb + (uint32_t)(kc & 1) * ST_STRIDE;
#pragma unroll
        for (int ks = 0; ks < 2; ks++) {
            uint32_t ah[2][4], al[2][4], bh[2][4], bl[2][4];
#pragma unroll
            for (int mi = 0; mi < 2; mi++) {
                uint32_t off = aRow + (uint32_t)(mi * 16 * 40 + ks * 16) * 2;
                ldsm4(ah[mi], st + ST_AH + off);
                ldsm4(al[mi], st + ST_AL + off);
            }
#pragma unroll
            for (int ni = 0; ni < 2; ni++) {
                uint32_t off = bRow + (uint32_t)(ni * 16 * 40 + ks * 16) * 2;
                ldsm4(bh[ni], st + ST_BH + off);
                ldsm4(bl[ni], st + ST_BL + off);
            }
#pragma unroll
            for (int mi = 0; mi < 2; mi++)
#pragma unroll
                for (int n2 = 0; n2 < 2; n2++)
#pragma unroll
                    for (int s = 0; s < 2; s++) {
                        uint32_t bhF[2] = {bh[n2][s], bh[n2][s + 2]};
                        uint32_t blF[2] = {bl[n2][s], bl[n2][s + 2]};
                        float* a = acc[mi][n2 * 2 + s];
                        mma16816(a, ah[mi], bhF);
                        mma16816(a, ah[mi], blF);
                        mma16816(a, al[mi], bhF);
                    }
        }
    };

    const int nk = K >> 5;
    load_stage(0);
    for (int kc = 0; kc < nk; kc++) {
        if (kc + 1 < nk) { load_stage(kc + 1); CP_WAIT(1); }
        else             { CP_WAIT(0); }
        __syncthreads();
        compute_stage(kc);
        __syncthreads();
    }

    const int g = lane >> 2, tg = lane & 3;
#pragma unroll
    for (int mi = 0; mi < 2; mi++) {
        size_t row = m0 + (size_t)(wm * 32 + mi * 16 + g);
#pragma unroll
        for (int ni = 0; ni < 4; ni++) {
            int col = n0 + wn * 32 + ni * 8 + tg * 2;
            if (!TAIL || col < N) {
                float* a = acc[mi][ni];
                size_t o0 = row * (size_t)ldc + col;
                size_t o1 = (row + 8) * (size_t)ldc + col;
                if (WF32) {
                    *(float2*)(C + o0) = make_float2(a[0], a[1]);
                    *(float2*)(C + o1) = make_float2(a[2], a[3]);
                }
                if (SPLIT) {
                    __nv_bfloat16 h0, l0, h1, l1, h2, l2, h3, l3;
                    split2(a[0], h0, l0); split2(a[1], h1, l1);
                    split2(a[2], h2, l2); split2(a[3], h3, l3);
                    *(__nv_bfloat162*)(Chi + o0) = __nv_bfloat162(h0, h1);
                    *(__nv_bfloat162*)(Clo + o0) = __nv_bfloat162(l0, l1);
                    *(__nv_bfloat162*)(Chi + o1) = __nv_bfloat162(h2, h3);
                    *(__nv_bfloat162*)(Clo + o1) = __nv_bfloat162(l2, l3);
                }
            }
        }
    }
}

// ---------------- causal depthwise conv(4) + silu -> bf16 split only -----
#define CONV_ROWS 16
__global__ __launch_bounds__(256) void conv_silu_kernel(
    const float* __restrict__ xz, const float* __restrict__ Wconv,
    const float* __restrict__ bconv,
    __nv_bfloat16* __restrict__ uh, __nv_bfloat16* __restrict__ ul)
{
    const int d = threadIdx.x;
    const int m0 = blockIdx.x * CONV_ROWS;
    const int l0 = m0 & (LQ - 1);
    const float w0 = Wconv[d * 4 + 0], w1 = Wconv[d * 4 + 1];
    const float w2 = Wconv[d * 4 + 2], w3 = Wconv[d * 4 + 3];
    const float bb = bconv[d];
    const float* base = xz + (size_t)m0 * (2 * D_INNER) + d;

    float x1 = (l0 >= 3) ? base[-3 * 2 * D_INNER] : 0.f;
    float x2 = (l0 >= 2) ? base[-2 * 2 * D_INNER] : 0.f;
    float x3 = (l0 >= 1) ? base[-1 * 2 * D_INNER] : 0.f;
#pragma unroll
    for (int r = 0; r < CONV_ROWS; r++) {
        float cur = base[(size_t)r * 2 * D_INNER];
        float acc = bb;
        acc = fmaf(w0, x1, acc); acc = fmaf(w1, x2, acc);
        acc = fmaf(w2, x3, acc); acc = fmaf(w3, cur, acc);
        float sv = __fdividef(acc, 1.f + __expf(-acc));
        size_t o = (size_t)(m0 + r) * D_INNER + d;
        __nv_bfloat16 h, lo; split2(sv, h, lo);
        uh[o] = h; ul[o] = lo;
        x1 = x2; x2 = x3; x3 = cur;
    }
}

// ---------------- chunked selective scan ----------------
// u is read as uh+ul (bf16 split). Pass C writes y split in place (per-lane
// trailing write, 4-step prefetch lead).
template <bool PASSC>
__global__ __launch_bounds__(128, 2) void scan_pass(
    const float* __restrict__ dbl,          // [M][40]: dt(8) | B(16) | C(16)
    __nv_bfloat16* uh_io, __nv_bfloat16* ul_io,
    const float* __restrict__ xz,           // z at col 256
    const float* __restrict__ Wdt, const float* __restrict__ bdt,
    const float* __restrict__ Alog, const float* __restrict__ Dp,
    float* __restrict__ pq_out, const float* __restrict__ pq_in)
{
    __shared__ __align__(16) float sdbl[2][16 * 40];

    const int b = blockIdx.x >> 1;
    const int d = ((blockIdx.x & 1) << 7) | threadIdx.x;
    const int ch = blockIdx.y;
    const int t0 = ch << 7;

    float wdt[8];
#pragma unroll
    for (int r = 0; r < 8; r++) wdt[r] = Wdt[d * 8 + r];
    const float bdtd = bdt[d];
    const float Dpd  = Dp[d];
    float Aneg[16];
#pragma unroll
    for (int n = 0; n < 16; n++) Aneg[n] = -__expf(Alog[d * 16 + n]);
    const float a0 = Aneg[0];
    float resid[16];
#pragma unroll
    for (int n = 0; n < 16; n++) resid[n] = fmaf(-(float)(n + 1), a0, Aneg[n]);

    __nv_bfloat16* uhd = uh_io + (size_t)b * LQ * D_INNER + d;
    __nv_bfloat16* uld = ul_io + (size_t)b * LQ * D_INNER + d;
    const float* zrd  = xz + (size_t)b * LQ * (2 * D_INNER) + D_INNER + d;
    const float* dsrc = dbl + (size_t)b * LQ * 40;

    float u_pf[4], z_pf[4];
#pragma unroll
    for (int i = 0; i < 4; i++) {
        size_t oo = (size_t)(t0 + i) * D_INNER;
        u_pf[i] = __bfloat162float(uhd[oo]) + __bfloat162float(uld[oo]);
        if (PASSC) z_pf[i] = zrd[(size_t)(t0 + i) * (2 * D_INNER)];
    }

    auto issue = [&](int c) {
        const float* src = dsrc + (size_t)c * 16 * 40;
        float* dst = sdbl[c & 1];
        int i = threadIdx.x;
        cp_async16(smem_u32(dst + i * 4), src + i * 4);
        if (i < 32) cp_async16(smem_u32(dst + (i + 128) * 4), src + (i + 128) * 4);
        CP_COMMIT();
    };
    const int c0 = ch << 3;
    issue(c0);
    issue(c0 + 1);

    float hst[16];
#pragma unroll
    for (int n = 0; n < 16; n++) hst[n] = 0.f;
    float dsum = 0.f;

    if (PASSC) {
        // fold prefix chunks 0..ch-1: h = P*h + q (overlaps with cp.async)
        for (int cc = 0; cc < ch; cc++) {
            size_t pb = ((size_t)(b * NCH + cc) * 32) * D_INNER + d;
#pragma unroll
            for (int n = 0; n < 16; n++)
                hst[n] = fmaf(pq_in[pb + (size_t)n * D_INNER], hst[n],
                              pq_in[pb + (size_t)(16 + n) * D_INNER]);
        }
    }

    for (int ci = 0; ci < 8; ci++) {
        if (ci < 7) CP_WAIT(1); else CP_WAIT(0);
        __syncthreads();
        const float* sh = sdbl[ci & 1];
#pragma unroll
        for (int s = 0; s < 16; s++) {
            const int t = t0 + (ci << 4) + s;
            float u_t = u_pf[s & 3];
            float z_t;
            if (PASSC) z_t = z_pf[s & 3];
            int tn = t + 4;
            if (tn < LQ) {
                size_t oo = (size_t)tn * D_INNER;
                u_pf[s & 3] = __bfloat162float(uhd[oo]) + __bfloat162float(uld[oo]);
                if (PASSC) z_pf[s & 3] = zrd[(size_t)tn * (2 * D_INNER)];
            }
            const float* row = sh + s * 40;
            float4 q0 = *(const float4*)(row);
            float4 q1 = *(const float4*)(row + 4);
            float xdt = bdtd;
            xdt = fmaf(q0.x, wdt[0], xdt); xdt = fmaf(q0.y, wdt[1], xdt);
            xdt = fmaf(q0.z, wdt[2], xdt); xdt = fmaf(q0.w, wdt[3], xdt);
            xdt = fmaf(q1.x, wdt[4], xdt); xdt = fmaf(q1.y, wdt[5], xdt);
            xdt = fmaf(q1.z, wdt[6], xdt); xdt = fmaf(q1.w, wdt[7], xdt);
            float delta = (xdt > 20.f) ? xdt : log1pf(__expf(xdt));
            float du = delta * u_t;

            float p = __expf(delta * a0);
            float pw[16];
            pw[0] = p;
#pragma unroll
            for (int n = 1; n < 16; n++) { int a = (n + 1) >> 1; pw[n] = pw[a - 1] * pw[n - a]; }

            float4 B0 = *(const float4*)(row + 8);
            float4 B1 = *(const float4*)(row + 12);
            float4 B2 = *(const float4*)(row + 16);
            float4 B3 = *(const float4*)(row + 20);
            float Bn[16] = {B0.x, B0.y, B0.z, B0.w, B1.x, B1.y, B1.z, B1.w,
                            B2.x, B2.y, B2.z, B2.w, B3.x, B3.y, B3.z, B3.w};
            if (PASSC) {
                float4 C0 = *(const float4*)(row + 24);
                float4 C1 = *(const float4*)(row + 28);
                float4 C2 = *(const float4*)(row + 32);
                float4 C3 = *(const float4*)(row + 36);
                float Cn[16] = {C0.x, C0.y, C0.z, C0.w, C1.x, C1.y, C1.z, C1.w,
                                C2.x, C2.y, C2.z, C2.w, C3.x, C3.y, C3.z, C3.w};
                float y0 = 0.f, y1 = 0.f;
#pragma unroll
                for (int n = 0; n < 16; n += 2) {
                    float dA0 = pw[n]     * fmaf(delta, resid[n],     1.f);
                    float dA1 = pw[n + 1] * fmaf(delta, resid[n + 1], 1.f);
                    hst[n]     = fmaf(dA0, hst[n],     du * Bn[n]);
                    hst[n + 1] = fmaf(dA1, hst[n + 1], du * Bn[n + 1]);
                    y0 = fmaf(hst[n],     Cn[n],     y0);
                    y1 = fmaf(hst[n + 1], Cn[n + 1], y1);
                }
                float sg = __fdividef(z_t, 1.f + __expf(-z_t));
                float yv = (y0 + y1 + u_t * Dpd) * sg;
                __nv_bfloat16 hh2, ll2; split2(yv, hh2, ll2);
                uhd[(size_t)t * D_INNER] = hh2;
                uld[(size_t)t * D_INNER] = ll2;
            } else {
#pragma unroll
                for (int n = 0; n < 16; n += 2) {
                    float dA0 = pw[n]     * fmaf(delta, resid[n],     1.f);
                    float dA1 = pw[n + 1] * fmaf(delta, resid[n + 1], 1.f);
                    hst[n]     = fmaf(dA0, hst[n],     du * Bn[n]);
                    hst[n + 1] = fmaf(dA1, hst[n + 1], du * Bn[n + 1]);
                }
                dsum += delta;
            }
        }
        __syncthreads();
        if (ci + 2 < 8) issue(c0 + ci + 2);
    }

    if (!PASSC) {
        size_t pb = ((size_t)(b * NCH + ch) * 32) * D_INNER + d;
#pragma unroll
        for (int n = 0; n < 16; n++) {
            pq_out[pb + (size_t)n * D_INNER]        = __expf(dsum * Aneg[n]);
            pq_out[pb + (size_t)(16 + n) * D_INNER] = hst[n];
        }
    }
}

// ---------------- mean over L + LayerNorm + classifier ----------------
__global__ __launch_bounds__(512) void head_kernel(
    const float* __restrict__ h, const float* __restrict__ g_ln,
    const float* __restrict__ b_ln, const float* __restrict__ Wc,
    const float* __restrict__ bc, float* __restrict__ out)
{
    const int b = blockIdx.x, tid = threadIdx.x;
    const int d = tid & 127, q = tid >> 7;
    __shared__ float part[4][128];
    __shared__ float red[128];
    __shared__ float mn[128];

    const float* p = h + (size_t)b * LQ * D_MODEL + (size_t)q * 256 * D_MODEL + d;
    float s = 0.f;
#pragma unroll 8
    for (int l = 0; l < 256; l++) s += p[(size_t)l * D_MODEL];
    part[q][d] = s;
    __syncthreads();

    if (tid < 128) {
        float m = (part[0][tid] + part[1][tid] + part[2][tid] + part[3][tid]) * (1.f / (float)LQ);
        red[tid] = m;
        mn[tid] = m;
    }
    __syncthreads();
    for (int off = 64; off > 0; off >>= 1) {
        if (tid < off) red[tid] += red[tid + off];
        __syncthreads();
    }
    float mu = red[0] * (1.f / 128.f);
    __syncthreads();
    if (tid < 128) { float dm = mn[tid] - mu; red[tid] = dm * dm; }
    __syncthreads();
    for (int off = 64; off > 0; off >>= 1) {
        if (tid < off) red[tid] += red[tid + off];
        __syncthreads();
    }
    float var = red[0] * (1.f / 128.f);
    float rs = rsqrtf(var + 1e-5f);
    __syncthreads();
    if (tid < 128) mn[tid] = (mn[tid] - mu) * rs * g_ln[tid] + b_ln[tid];
    __syncthreads();
    if (tid < 10) {
        float a = bc[tid];
        const float* w = Wc + tid * 128;
#pragma unroll 8
        for (int dd = 0; dd < 128; dd++) a = fmaf(mn[dd], w[dd], a);
        out[b * 10 + tid] = a;
    }
}

// ---------------- orchestration ----------------
extern "C" void kernel_launch(void* const* d_in, const int* in_sizes, int n_in,
                              void* d_out, int out_size)
{
    const float* x     = (const float*)d_in[0];
    const float* Wp    = (const float*)d_in[1];
    const float* bp    = (const float*)d_in[2];
    const float* Win   = (const float*)d_in[3];
    const float* Wconv = (const float*)d_in[4];
    const float* bconv = (const float*)d_in[5];
    const float* Wx    = (const float*)d_in[6];
    const float* Wdt   = (const float*)d_in[7];
    const float* bdt   = (const float*)d_in[8];
    const float* Alog  = (const float*)d_in[9];
    const float* Dp    = (const float*)d_in[10];
    const float* Wo    = (const float*)d_in[11];
    const float* gln   = (const float*)d_in[12];
    const float* bln   = (const float*)d_in[13];
    const float* Wc    = (const float*)d_in[14];
    const float* bc    = (const float*)d_in[15];
    float* out = (float*)d_out;

    float *h, *xzb, *dblb, *pqb;
    __nv_bfloat16 *hh, *hl, *uh, *ul, *winh, *winl, *wxh, *wxl, *woh, *wol;
    cudaGetSymbolAddress((void**)&h,    g_h);
    cudaGetSymbolAddress((void**)&xzb,  g_xz);
    cudaGetSymbolAddress((void**)&dblb, g_dbl);
    cudaGetSymbolAddress((void**)&pqb,  g_pq);
    cudaGetSymbolAddress((void**)&hh,   g_hh);
    cudaGetSymbolAddress((void**)&hl,   g_hl);
    cudaGetSymbolAddress((void**)&uh,   g_uh);
    cudaGetSymbolAddress((void**)&ul,   g_ul);
    cudaGetSymbolAddress((void**)&winh, g_winh);
    cudaGetSymbolAddress((void**)&winl, g_winl);
    cudaGetSymbolAddress((void**)&wxh,  g_wxh);
    cudaGetSymbolAddress((void**)&wxl,  g_wxl);
    cudaGetSymbolAddress((void**)&woh,  g_woh);
    cudaGetSymbolAddress((void**)&wol,  g_wol);

    cudaFuncSetAttribute((const void*)mma_gemm<false, true, false>, cudaFuncAttributeMaxDynamicSharedMemorySize, GEMM_SMEM);
    cudaFuncSetAttribute((const void*)mma_gemm<false, true, true>,  cudaFuncAttributeMaxDynamicSharedMemorySize, GEMM_SMEM);
    cudaFuncSetAttribute((const void*)mma_gemm<true, false, false>, cudaFuncAttributeMaxDynamicSharedMemorySize, GEMM_SMEM);

    prep_kernel<<<EMBED_BLOCKS + SPLIT_BLOCKS, 256>>>(
        x, Wp, bp, Win, Wx, Wo, hh, hl, winh, winl, wxh, wxl, woh, wol);

    for (int i = 0; i < N_LAYERS; i++) {
        const bool last = (i == N_LAYERS - 1);
        // xz = h @ Win^T   (M=65536, N=512, K=128) — full tiles
        mma_gemm<false, true, false><<<dim3(M_TOT / 128, 8), 256, GEMM_SMEM>>>(
            hh, hl, winh + (size_t)i * 512 * 128, winl + (size_t)i * 512 * 128,
            xzb, nullptr, nullptr, 512, 128, 512);
        // depthwise conv + silu -> bf16 split u only
        conv_silu_kernel<<<M_TOT / CONV_ROWS, 256>>>(
            xzb, Wconv + (size_t)i * D_INNER * 4, bconv + (size_t)i * D_INNER, uh, ul);
        // dbl = u @ Wx^T   (N=40, K=256) — tail tile
        mma_gemm<false, true, true><<<dim3(M_TOT / 128, 1), 256, GEMM_SMEM>>>(
            uh, ul, wxh + (size_t)i * 40 * 256, wxl + (size_t)i * 40 * 256,
            dblb, nullptr, nullptr, 40, 256, 40);
        // chunked scan: pass A (chunks 0..6, q + telescoped P), pass C (fold prefix + emit y)
        scan_pass<false><<<dim3(128, NCH - 1), 128>>>(
            dblb, uh, ul, xzb,
            Wdt + (size_t)i * D_INNER * DT_RANK, bdt + (size_t)i * D_INNER,
            Alog + (size_t)i * D_INNER * D_STATE, Dp + (size_t)i * D_INNER,
            pqb, nullptr);
        scan_pass<true><<<dim3(128, NCH), 128>>>(
            dblb, uh, ul, xzb,
            Wdt + (size_t)i * D_INNER * DT_RANK, bdt + (size_t)i * D_INNER,
            Alog + (size_t)i * D_INNER * D_STATE, Dp + (size_t)i * D_INNER,
            nullptr, pqb);
        // h = y @ Wo^T    (N=128, K=256) — full tiles
        if (last)
            mma_gemm<false, true, false><<<dim3(M_TOT / 128, 2), 256, GEMM_SMEM>>>(
                uh, ul, woh + (size_t)i * 128 * 256, wol + (size_t)i * 128 * 256,
                h, nullptr, nullptr, 128, 256, 128);
        else
            mma_gemm<true, false, false><<<dim3(M_TOT / 128, 2), 256, GEMM_SMEM>>>(
                uh, ul, woh + (size_t)i * 128 * 256, wol + (size_t)i * 128 * 256,
                nullptr, hh, hl, 128, 256, 128);
    }

    head_kernel<<<BATCH, 512>>>(h, gln, bln, Wc, bc, out);
}

// round 11
// speedup vs baseline: 1.2492x; 1.1178x over previous
#include <cuda_runtime.h>
#include <cuda_bf16.h>
#include <cstdint>

#define D_MODEL 128
#define D_INNER 256
#define D_STATE 16
#define DT_RANK 8
#define N_LAYERS 4
#define LQ      1024
#define BATCH   64
#define M_TOT   (BATCH * LQ)   /* 65536 rows */
#define NCH     8              /* scan chunks */

typedef unsigned long long u64;

// ---------------- static scratch (no allocation allowed) ----------------
__device__ __align__(256) float g_h  [(size_t)M_TOT * D_MODEL];        // fp32 h (head input, last layer)
__device__ __align__(256) float g_xz [(size_t)M_TOT * 2 * D_INNER];    // (u_raw | z)
__device__ __align__(256) float g_dbl[(size_t)M_TOT * 40];             // dt|B|C
__device__ __align__(256) float g_pq [(size_t)BATCH * NCH * 32 * D_INNER]; // P|q per chunk
__device__ __align__(256) __nv_bfloat16 g_hh[(size_t)M_TOT * D_MODEL];
__device__ __align__(256) __nv_bfloat16 g_hl[(size_t)M_TOT * D_MODEL];
__device__ __align__(256) __nv_bfloat16 g_uh[(size_t)M_TOT * D_INNER]; // u split, then y split (in-place)
__device__ __align__(256) __nv_bfloat16 g_ul[(size_t)M_TOT * D_INNER];
__device__ __align__(256) __nv_bfloat16 g_winh[N_LAYERS * 512 * 128];
__device__ __align__(256) __nv_bfloat16 g_winl[N_LAYERS * 512 * 128];
__device__ __align__(256) __nv_bfloat16 g_wxh [N_LAYERS * 40 * 256];
__device__ __align__(256) __nv_bfloat16 g_wxl [N_LAYERS * 40 * 256];
__device__ __align__(256) __nv_bfloat16 g_woh [N_LAYERS * 128 * 256];
__device__ __align__(256) __nv_bfloat16 g_wol [N_LAYERS * 128 * 256];

// ---------------- PTX helpers ----------------
__device__ __forceinline__ uint32_t smem_u32(const void* p) {
    uint32_t a;
    asm("{ .reg .u64 t; cvta.to.shared.u64 t, %1; cvt.u32.u64 %0, t; }" : "=r"(a) : "l"(p));
    return a;
}
__device__ __forceinline__ void cp_async16(uint32_t saddr, const void* gmem) {
    asm volatile("cp.async.ca.shared.global [%0], [%1], 16;\n" :: "r"(saddr), "l"(gmem));
}
__device__ __forceinline__ void cp_async16z(uint32_t saddr, const void* gmem, int sz) {
    asm volatile("cp.async.ca.shared.global [%0], [%1], 16, %2;\n" :: "r"(saddr), "l"(gmem), "r"(sz));
}
#define CP_COMMIT()  asm volatile("cp.async.commit_group;\n" ::)
#define CP_WAIT(n)   asm volatile("cp.async.wait_group %0;\n" :: "n"(n) : "memory")

__device__ __forceinline__ void ldsm4(uint32_t* r, uint32_t addr) {
    asm volatile("ldmatrix.sync.aligned.m8n8.x4.shared.b16 {%0,%1,%2,%3}, [%4];"
        : "=r"(r[0]), "=r"(r[1]), "=r"(r[2]), "=r"(r[3]) : "r"(addr));
}
__device__ __forceinline__ void mma16816(float* c, const uint32_t* a, const uint32_t* b) {
    asm volatile("mma.sync.aligned.m16n8k16.row.col.f32.bf16.bf16.f32 "
        "{%0,%1,%2,%3}, {%4,%5,%6,%7}, {%8,%9}, {%0,%1,%2,%3};"
        : "+f"(c[0]), "+f"(c[1]), "+f"(c[2]), "+f"(c[3])
        : "r"(a[0]), "r"(a[1]), "r"(a[2]), "r"(a[3]), "r"(b[0]), "r"(b[1]));
}

// ---------------- f32x2 packed math (FFMA2 path) ----------------
__device__ __forceinline__ u64 pack2(float lo, float hi) {
    u64 r; asm("mov.b64 %0, {%1, %2};" : "=l"(r) : "f"(lo), "f"(hi)); return r;
}
__device__ __forceinline__ void unpack2(u64 v, float& lo, float& hi) {
    asm("mov.b64 {%0, %1}, %2;" : "=f"(lo), "=f"(hi) : "l"(v));
}
__device__ __forceinline__ u64 fma2(u64 a, u64 b, u64 c) {
    u64 d; asm("fma.rn.f32x2 %0, %1, %2, %3;" : "=l"(d) : "l"(a), "l"(b), "l"(c)); return d;
}
__device__ __forceinline__ u64 mul2(u64 a, u64 b) {
    u64 d; asm("mul.rn.f32x2 %0, %1, %2;" : "=l"(d) : "l"(a), "l"(b)); return d;
}

// ---------------- fp32 -> bf16 hi/lo split ----------------
__device__ __forceinline__ void split2(float v, __nv_bfloat16& h, __nv_bfloat16& l) {
    h = __float2bfloat16(v);
    l = __float2bfloat16(v - __bfloat162float(h));
}

// ---------------- prep: weight split + embed in one launch ----------------
#define EMBED_BLOCKS 8192
#define SPLIT_BLOCKS 1696
__global__ __launch_bounds__(256) void prep_kernel(
    const float* __restrict__ x, const float* __restrict__ Wp,
    const float* __restrict__ bp,
    const float* __restrict__ Win, const float* __restrict__ Wx,
    const float* __restrict__ Wo,
    __nv_bfloat16* __restrict__ hh,   __nv_bfloat16* __restrict__ hl,
    __nv_bfloat16* __restrict__ winh, __nv_bfloat16* __restrict__ winl,
    __nv_bfloat16* __restrict__ wxh,  __nv_bfloat16* __restrict__ wxl,
    __nv_bfloat16* __restrict__ woh,  __nv_bfloat16* __restrict__ wol)
{
    if (blockIdx.x < EMBED_BLOCKS) {
        int i = blockIdx.x * 256 + threadIdx.x;
        int m = i >> 5, dq = (i & 31) << 2;
        float xv = x[m];
        size_t o = (size_t)m * D_MODEL + dq;
        __nv_bfloat16 h0, l0, h1, l1, h2, l2, h3, l3;
        split2(fmaf(xv, Wp[dq + 0], bp[dq + 0]), h0, l0);
        split2(fmaf(xv, Wp[dq + 1], bp[dq + 1]), h1, l1);
        split2(fmaf(xv, Wp[dq + 2], bp[dq + 2]), h2, l2);
        split2(fmaf(xv, Wp[dq + 3], bp[dq + 3]), h3, l3);
        *(__nv_bfloat162*)(hh + o)     = __nv_bfloat162(h0, h1);
        *(__nv_bfloat162*)(hh + o + 2) = __nv_bfloat162(h2, h3);
        *(__nv_bfloat162*)(hl + o)     = __nv_bfloat162(l0, l1);
        *(__nv_bfloat162*)(hl + o + 2) = __nv_bfloat162(l2, l3);
    } else {
        const int nWin = N_LAYERS * 512 * 128;
        const int nWx  = N_LAYERS * 40 * 256;
        const int nWo  = N_LAYERS * 128 * 256;
        const int total = nWin + nWx + nWo;
        int i = (blockIdx.x - EMBED_BLOCKS) * 256 + threadIdx.x;
        if (i < total) {
            const float* s; __nv_bfloat16 *dh, *dl; int j;
            if (i < nWin)            { s = Win; dh = winh; dl = winl; j = i; }
            else if (i < nWin + nWx) { s = Wx;  dh = wxh;  dl = wxl;  j = i - nWin; }
            else                     { s = Wo;  dh = woh;  dl = wol;  j = i - nWin - nWx; }
            __nv_bfloat16 h, l; split2(s[j], h, l);
            dh[j] = h; dl[j] = l;
        }
    }
}

// ================= split-bf16 GEMM via mma.sync (HMMA) =================
#define ST_AH 0
#define ST_AL 10240
#define ST_BH 20480
#define ST_BL 25600
#define ST_STRIDE 30720
#define GEMM_SMEM 61440

template <bool SPLIT, bool WF32, bool TAIL>
__global__ __launch_bounds__(256) void mma_gemm(
    const __nv_bfloat16* __restrict__ Ahi, const __nv_bfloat16* __restrict__ Alo,
    const __nv_bfloat16* __restrict__ Bhi, const __nv_bfloat16* __restrict__ Blo,
    float* __restrict__ C, __nv_bfloat16* __restrict__ Chi,
    __nv_bfloat16* __restrict__ Clo, int N, int K, int ldc)
{
    extern __shared__ __align__(128) __nv_bfloat16 smem[];
    const int tid = threadIdx.x;
    const int lane = tid & 31, wid = tid >> 5;
    const int wm = wid >> 1, wn = wid & 1;
    const size_t m0 = (size_t)blockIdx.x * 128;
    const int n0 = blockIdx.y * 64;
    const int nValid = TAIL ? ((N - n0) < 64 ? (N - n0) : 64) : 64;

    const __nv_bfloat16* aH = Ahi + m0 * K;
    const __nv_bfloat16* aL = Alo + m0 * K;
    const __nv_bfloat16* bH = Bhi + (size_t)n0 * K;
    const __nv_bfloat16* bL = Blo + (size_t)n0 * K;
    const uint32_t sb = smem_u32(smem);

    float acc[2][4][4];
#pragma unroll
    for (int i = 0; i < 2; i++)
#pragma unroll
        for (int j = 0; j < 4; j++)
#pragma unroll
            for (int k = 0; k < 4; k++) acc[i][j][k] = 0.f;

    auto load_stage = [&](int kc) {
        const uint32_t st = (uint32_t)(kc & 1) * ST_STRIDE;
        const int k0 = kc << 5;
#pragma unroll
        for (int j = 0; j < 6; j++) {
            int i = tid + j * 256;
            int r, c; uint32_t dofs; const __nv_bfloat16* src; int sz = 16;
            if (i < 512)        { r = i >> 2;             c = i & 3; dofs = st + ST_AH + (uint32_t)(r * 40 + c * 8) * 2; src = aH + (size_t)r * K + k0 + c * 8; }
            else if (i < 1024)  { int q = i - 512;  r = q >> 2; c = q & 3; dofs = st + ST_AL + (uint32_t)(r * 40 + c * 8) * 2; src = aL + (size_t)r * K + k0 + c * 8; }
            else if (i < 1280)  { int q = i - 1024; r = q >> 2; c = q & 3; dofs = st + ST_BH + (uint32_t)(r * 40 + c * 8) * 2;
                                  if (TAIL) { int rr = r < nValid ? r : 0; src = bH + (size_t)rr * K + k0 + c * 8; if (r >= nValid) sz = 0; }
                                  else       src = bH + (size_t)r * K + k0 + c * 8; }
            else                { int q = i - 1280; r = q >> 2; c = q & 3; dofs = st + ST_BL + (uint32_t)(r * 40 + c * 8) * 2;
                                  if (TAIL) { int rr = r < nValid ? r : 0; src = bL + (size_t)rr * K + k0 + c * 8; if (r >= nValid) sz = 0; }
                                  else       src = bL + (size_t)r * K + k0 + c * 8; }
            if (TAIL) cp_async16z(sb + dofs, src, sz);
            else      cp_async16 (sb + dofs, src);
        }
        CP_COMMIT();
    };

    const uint32_t aRow = (uint32_t)((wm * 32 + (lane & 15)) * 40 + (lane >> 4) * 8) * 2;
    const uint32_t bRow = (uint32_t)((wn * 32 + (lane & 15)) * 40 + (lane >> 4) * 8) * 2;

    auto compute_stage = [&](int kc) {
        const uint32_t st = sb + (uint32_t)(kc & 1) * ST_STRIDE;
#pragma unroll
        for (int ks = 0; ks < 2; ks++) {
            uint32_t ah[2][4], al[2][4], bh[2][4], bl[2][4];
#pragma unroll
            for (int mi = 0; mi < 2; mi++) {
                uint32_t off = aRow + (uint32_t)(mi * 16 * 40 + ks * 16) * 2;
                ldsm4(ah[mi], st + ST_AH + off);
                ldsm4(al[mi], st + ST_AL + off);
            }
#pragma unroll
            for (int ni = 0; ni < 2; ni++) {
                uint32_t off = bRow + (uint32_t)(ni * 16 * 40 + ks * 16) * 2;
                ldsm4(bh[ni], st + ST_BH + off);
                ldsm4(bl[ni], st + ST_BL + off);
            }
#pragma unroll
            for (int mi = 0; mi < 2; mi++)
#pragma unroll
                for (int n2 = 0; n2 < 2; n2++)
#pragma unroll
                    for (int s = 0; s < 2; s++) {
                        uint32_t bhF[2] = {bh[n2][s], bh[n2][s + 2]};
                        uint32_t blF[2] = {bl[n2][s], bl[n2][s + 2]};
                        float* a = acc[mi][n2 * 2 + s];
                        mma16816(a, ah[mi], bhF);
                        mma16816(a, ah[mi], blF);
                        mma16816(a, al[mi], bhF);
                    }
        }
    };

    const int nk = K >> 5;
    load_stage(0);
    for (int kc = 0; kc < nk; kc++) {
        if (kc + 1 < nk) { load_stage(kc + 1); CP_WAIT(1); }
        else             { CP_WAIT(0); }
        __syncthreads();
        compute_stage(kc);
        __syncthreads();
    }

    const int g = lane >> 2, tg = lane & 3;
#pragma unroll
    for (int mi = 0; mi < 2; mi++) {
        size_t row = m0 + (size_t)(wm * 32 + mi * 16 + g);
#pragma unroll
        for (int ni = 0; ni < 4; ni++) {
            int col = n0 + wn * 32 + ni * 8 + tg * 2;
            if (!TAIL || col < N) {
                float* a = acc[mi][ni];
                size_t o0 = row * (size_t)ldc + col;
                size_t o1 = (row + 8) * (size_t)ldc + col;
                if (WF32) {
                    *(float2*)(C + o0) = make_float2(a[0], a[1]);
                    *(float2*)(C + o1) = make_float2(a[2], a[3]);
                }
                if (SPLIT) {
                    __nv_bfloat16 h0, l0, h1, l1, h2, l2, h3, l3;
                    split2(a[0], h0, l0); split2(a[1], h1, l1);
                    split2(a[2], h2, l2); split2(a[3], h3, l3);
                    *(__nv_bfloat162*)(Chi + o0) = __nv_bfloat162(h0, h1);
                    *(__nv_bfloat162*)(Clo + o0) = __nv_bfloat162(l0, l1);
                    *(__nv_bfloat162*)(Chi + o1) = __nv_bfloat162(h2, h3);
                    *(__nv_bfloat162*)(Clo + o1) = __nv_bfloat162(l2, l3);
                }
            }
        }
    }
}

// ---------------- causal depthwise conv(4) + silu -> bf16 split only -----
#define CONV_ROWS 16
__global__ __launch_bounds__(256) void conv_silu_kernel(
    const float* __restrict__ xz, const float* __restrict__ Wconv,
    const float* __restrict__ bconv,
    __nv_bfloat16* __restrict__ uh, __nv_bfloat16* __restrict__ ul)
{
    const int d = threadIdx.x;
    const int m0 = blockIdx.x * CONV_ROWS;
    const int l0 = m0 & (LQ - 1);
    const float w0 = Wconv[d * 4 + 0], w1 = Wconv[d * 4 + 1];
    const float w2 = Wconv[d * 4 + 2], w3 = Wconv[d * 4 + 3];
    const float bb = bconv[d];
    const float* base = xz + (size_t)m0 * (2 * D_INNER) + d;

    float x1 = (l0 >= 3) ? base[-3 * 2 * D_INNER] : 0.f;
    float x2 = (l0 >= 2) ? base[-2 * 2 * D_INNER] : 0.f;
    float x3 = (l0 >= 1) ? base[-1 * 2 * D_INNER] : 0.f;
#pragma unroll
    for (int r = 0; r < CONV_ROWS; r++) {
        float cur = base[(size_t)r * 2 * D_INNER];
        float acc = bb;
        acc = fmaf(w0, x1, acc); acc = fmaf(w1, x2, acc);
        acc = fmaf(w2, x3, acc); acc = fmaf(w3, cur, acc);
        float sv = __fdividef(acc, 1.f + __expf(-acc));
        size_t o = (size_t)(m0 + r) * D_INNER + d;
        __nv_bfloat16 h, lo; split2(sv, h, lo);
        uh[o] = h; ul[o] = lo;
        x1 = x2; x2 = x3; x3 = cur;
    }
}

// ---------------- chunked selective scan (f32x2-packed state math) -------
template <bool PASSC>
__global__ __launch_bounds__(128, 2) void scan_pass(
    const float* __restrict__ dbl,          // [M][40]: dt(8) | B(16) | C(16)
    __nv_bfloat16* uh_io, __nv_bfloat16* ul_io,
    const float* __restrict__ xz,           // z at col 256
    const float* __restrict__ Wdt, const float* __restrict__ bdt,
    const float* __restrict__ Alog, const float* __restrict__ Dp,
    float* __restrict__ pq_out, const float* __restrict__ pq_in)
{
    __shared__ __align__(16) float sdbl[2][16 * 40];

    const int b = blockIdx.x >> 1;
    const int d = ((blockIdx.x & 1) << 7) | threadIdx.x;
    const int ch = blockIdx.y;
    const int t0 = ch << 7;

    u64 wdt2[4];
#pragma unroll
    for (int r = 0; r < 4; r++) wdt2[r] = pack2(Wdt[d * 8 + 2 * r], Wdt[d * 8 + 2 * r + 1]);
    const u64 bdt2 = pack2(bdt[d], 0.f);
    const float Dpd = Dp[d];
    float Aneg[16];
#pragma unroll
    for (int n = 0; n < 16; n++) Aneg[n] = -__expf(Alog[d * 16 + n]);
    const float a0 = Aneg[0];
    u64 resid2[8];
#pragma unroll
    for (int i = 0; i < 8; i++)
        resid2[i] = pack2(fmaf(-(float)(2 * i + 1), a0, Aneg[2 * i]),
                          fmaf(-(float)(2 * i + 2), a0, Aneg[2 * i + 1]));
    const u64 one2 = pack2(1.f, 1.f);

    __nv_bfloat16* uhd = uh_io + (size_t)b * LQ * D_INNER + d;
    __nv_bfloat16* uld = ul_io + (size_t)b * LQ * D_INNER + d;
    const float* zrd  = xz + (size_t)b * LQ * (2 * D_INNER) + D_INNER + d;
    const float* dsrc = dbl + (size_t)b * LQ * 40;

    float u_pf[4], z_pf[4];
#pragma unroll
    for (int i = 0; i < 4; i++) {
        size_t oo = (size_t)(t0 + i) * D_INNER;
        u_pf[i] = __bfloat162float(uhd[oo]) + __bfloat162float(uld[oo]);
        if (PASSC) z_pf[i] = zrd[(size_t)(t0 + i) * (2 * D_INNER)];
    }

    auto issue = [&](int c) {
        const float* src = dsrc + (size_t)c * 16 * 40;
        float* dst = sdbl[c & 1];
        int i = threadIdx.x;
        cp_async16(smem_u32(dst + i * 4), src + i * 4);
        if (i < 32) cp_async16(smem_u32(dst + (i + 128) * 4), src + (i + 128) * 4);
        CP_COMMIT();
    };
    const int c0 = ch << 3;
    issue(c0);
    issue(c0 + 1);

    u64 hst2[8];
#pragma unroll
    for (int i = 0; i < 8; i++) hst2[i] = pack2(0.f, 0.f);
    float dsum = 0.f;

    if (PASSC) {
        // fold prefix chunks 0..ch-1: h = P*h + q (overlaps with cp.async)
        for (int cc = 0; cc < ch; cc++) {
            size_t pb = ((size_t)(b * NCH + cc) * 32) * D_INNER + d;
#pragma unroll
            for (int i = 0; i < 8; i++) {
                u64 P2 = pack2(pq_in[pb + (size_t)(2 * i) * D_INNER],
                               pq_in[pb + (size_t)(2 * i + 1) * D_INNER]);
                u64 q2 = pack2(pq_in[pb + (size_t)(16 + 2 * i) * D_INNER],
                               pq_in[pb + (size_t)(16 + 2 * i + 1) * D_INNER]);
                hst2[i] = fma2(P2, hst2[i], q2);
            }
        }
    }

    for (int ci = 0; ci < 8; ci++) {
        if (ci < 7) CP_WAIT(1); else CP_WAIT(0);
        __syncthreads();
        const float* sh = sdbl[ci & 1];
#pragma unroll
        for (int s = 0; s < 16; s++) {
            const int t = t0 + (ci << 4) + s;
            float u_t = u_pf[s & 3];
            float z_t;
            if (PASSC) z_t = z_pf[s & 3];
            int tn = t + 4;
            if (tn < LQ) {
                size_t oo = (size_t)tn * D_INNER;
                u_pf[s & 3] = __bfloat162float(uhd[oo]) + __bfloat162float(uld[oo]);
                if (PASSC) z_pf[s & 3] = zrd[(size_t)tn * (2 * D_INNER)];
            }
            const float* row = sh + s * 40;

            // xdt = bdt + dt . wdt  (packed, 4 fma2 + horizontal add)
            ulonglong2 dt0 = *(const ulonglong2*)(row);
            ulonglong2 dt1 = *(const ulonglong2*)(row + 4);
            u64 acc2 = fma2(dt0.x, wdt2[0], bdt2);
            acc2 = fma2(dt0.y, wdt2[1], acc2);
            acc2 = fma2(dt1.x, wdt2[2], acc2);
            acc2 = fma2(dt1.y, wdt2[3], acc2);
            float xl, xh; unpack2(acc2, xl, xh);
            float xdt = xl + xh;
            float delta = (xdt > 20.f) ? xdt : __logf(1.f + __expf(xdt));
            float du = delta * u_t;
            const u64 delta2 = pack2(delta, delta);
            const u64 du2 = pack2(du, du);

            // pw[i] = (p^(2i+1), p^(2i+2)), p = exp(delta*a0)
            float pp = __expf(delta * a0);
            float qq = pp * pp;
            u64 pw0 = pack2(pp, qq);
            u64 qb = pack2(qq, qq);
            u64 pw1 = mul2(pw0, qb);
            float q4f = qq * qq;
            u64 q4b = pack2(q4f, q4f);
            u64 pw2_ = mul2(pw0, q4b);
            u64 pw3 = mul2(pw1, q4b);
            float q8f = q4f * q4f;
            u64 q8b = pack2(q8f, q8f);
            u64 pw[8] = {pw0, pw1, pw2_, pw3,
                         mul2(pw0, q8b), mul2(pw1, q8b), mul2(pw2_, q8b), mul2(pw3, q8b)};

            ulonglong2 Bv0 = *(const ulonglong2*)(row + 8);
            ulonglong2 Bv1 = *(const ulonglong2*)(row + 12);
            ulonglong2 Bv2 = *(const ulonglong2*)(row + 16);
            ulonglong2 Bv3 = *(const ulonglong2*)(row + 20);
            u64 b2[8] = {Bv0.x, Bv0.y, Bv1.x, Bv1.y, Bv2.x, Bv2.y, Bv3.x, Bv3.y};

            if (PASSC) {
                ulonglong2 Cv0 = *(const ulonglong2*)(row + 24);
                ulonglong2 Cv1 = *(const ulonglong2*)(row + 28);
                ulonglong2 Cv2 = *(const ulonglong2*)(row + 32);
                ulonglong2 Cv3 = *(const ulonglong2*)(row + 36);
                u64 c2[8] = {Cv0.x, Cv0.y, Cv1.x, Cv1.y, Cv2.x, Cv2.y, Cv3.x, Cv3.y};
                u64 y2 = pack2(0.f, 0.f);
#pragma unroll
                for (int i = 0; i < 8; i++) {
                    u64 dA2 = mul2(pw[i], fma2(delta2, resid2[i], one2));
                    hst2[i] = fma2(dA2, hst2[i], mul2(du2, b2[i]));
                    y2 = fma2(hst2[i], c2[i], y2);
                }
                float y0, y1; unpack2(y2, y0, y1);
                float sg = __fdividef(z_t, 1.f + __expf(-z_t));
                float yv = (y0 + y1 + u_t * Dpd) * sg;
                __nv_bfloat16 hh2, ll2; split2(yv, hh2, ll2);
                uhd[(size_t)t * D_INNER] = hh2;
                uld[(size_t)t * D_INNER] = ll2;
            } else {
#pragma unroll
                for (int i = 0; i < 8; i++) {
                    u64 dA2 = mul2(pw[i], fma2(delta2, resid2[i], one2));
                    hst2[i] = fma2(dA2, hst2[i], mul2(du2, b2[i]));
                }
                dsum += delta;
            }
        }
        __syncthreads();
        if (ci + 2 < 8) issue(c0 + ci + 2);
    }

    if (!PASSC) {
        size_t pb = ((size_t)(b * NCH + ch) * 32) * D_INNER + d;
        float hv[16];
#pragma unroll
        for (int i = 0; i < 8; i++) unpack2(hst2[i], hv[2 * i], hv[2 * i + 1]);
#pragma unroll
        for (int n = 0; n < 16; n++) {
            pq_out[pb + (size_t)n * D_INNER]        = __expf(dsum * Aneg[n]);
            pq_out[pb + (size_t)(16 + n) * D_INNER] = hv[n];
        }
    }
}

// ---------------- mean over L + LayerNorm + classifier ----------------
__global__ __launch_bounds__(512) void head_kernel(
    const float* __restrict__ h, const float* __restrict__ g_ln,
    const float* __restrict__ b_ln, const float* __restrict__ Wc,
    const float* __restrict__ bc, float* __restrict__ out)
{
    const int b = blockIdx.x, tid = threadIdx.x;
    const int d = tid & 127, q = tid >> 7;
    __shared__ float part[4][128];
    __shared__ float red[128];
    __shared__ float mn[128];

    const float* p = h + (size_t)b * LQ * D_MODEL + (size_t)q * 256 * D_MODEL + d;
    float s = 0.f;
#pragma unroll 8
    for (int l = 0; l < 256; l++) s += p[(size_t)l * D_MODEL];
    part[q][d] = s;
    __syncthreads();

    if (tid < 128) {
        float m = (part[0][tid] + part[1][tid] + part[2][tid] + part[3][tid]) * (1.f / (float)LQ);
        red[tid] = m;
        mn[tid] = m;
    }
    __syncthreads();
    for (int off = 64; off > 0; off >>= 1) {
        if (tid < off) red[tid] += red[tid + off];
        __syncthreads();
    }
    float mu = red[0] * (1.f / 128.f);
    __syncthreads();
    if (tid < 128) { float dm = mn[tid] - mu; red[tid] = dm * dm; }
    __syncthreads();
    for (int off = 64; off > 0; off >>= 1) {
        if (tid < off) red[tid] += red[tid + off];
        __syncthreads();
    }
    float var = red[0] * (1.f / 128.f);
    float rs = rsqrtf(var + 1e-5f);
    __syncthreads();
    if (tid < 128) mn[tid] = (mn[tid] - mu) * rs * g_ln[tid] + b_ln[tid];
    __syncthreads();
    if (tid < 10) {
        float a = bc[tid];
        const float* w = Wc + tid * 128;
#pragma unroll 8
        for (int dd = 0; dd < 128; dd++) a = fmaf(mn[dd], w[dd], a);
        out[b * 10 + tid] = a;
    }
}

// ---------------- orchestration ----------------
extern "C" void kernel_launch(void* const* d_in, const int* in_sizes, int n_in,
                              void* d_out, int out_size)
{
    const float* x     = (const float*)d_in[0];
    const float* Wp    = (const float*)d_in[1];
    const float* bp    = (const float*)d_in[2];
    const float* Win   = (const float*)d_in[3];
    const float* Wconv = (const float*)d_in[4];
    const float* bconv = (const float*)d_in[5];
    const float* Wx    = (const float*)d_in[6];
    const float* Wdt   = (const float*)d_in[7];
    const float* bdt   = (const float*)d_in[8];
    const float* Alog  = (const float*)d_in[9];
    const float* Dp    = (const float*)d_in[10];
    const float* Wo    = (const float*)d_in[11];
    const float* gln   = (const float*)d_in[12];
    const float* bln   = (const float*)d_in[13];
    const float* Wc    = (const float*)d_in[14];
    const float* bc    = (const float*)d_in[15];
    float* out = (float*)d_out;

    float *h, *xzb, *dblb, *pqb;
    __nv_bfloat16 *hh, *hl, *uh, *ul, *winh, *winl, *wxh, *wxl, *woh, *wol;
    cudaGetSymbolAddress((void**)&h,    g_h);
    cudaGetSymbolAddress((void**)&xzb,  g_xz);
    cudaGetSymbolAddress((void**)&dblb, g_dbl);
    cudaGetSymbolAddress((void**)&pqb,  g_pq);
    cudaGetSymbolAddress((void**)&hh,   g_hh);
    cudaGetSymbolAddress((void**)&hl,   g_hl);
    cudaGetSymbolAddress((void**)&uh,   g_uh);
    cudaGetSymbolAddress((void**)&ul,   g_ul);
    cudaGetSymbolAddress((void**)&winh, g_winh);
    cudaGetSymbolAddress((void**)&winl, g_winl);
    cudaGetSymbolAddress((void**)&wxh,  g_wxh);
    cudaGetSymbolAddress((void**)&wxl,  g_wxl);
    cudaGetSymbolAddress((void**)&woh,  g_woh);
    cudaGetSymbolAddress((void**)&wol,  g_wol);

    cudaFuncSetAttribute((const void*)mma_gemm<false, true, false>, cudaFuncAttributeMaxDynamicSharedMemorySize, GEMM_SMEM);
    cudaFuncSetAttribute((const void*)mma_gemm<false, true, true>,  cudaFuncAttributeMaxDynamicSharedMemorySize, GEMM_SMEM);
    cudaFuncSetAttribute((const void*)mma_gemm<true, false, false>, cudaFuncAttributeMaxDynamicSharedMemorySize, GEMM_SMEM);

    prep_kernel<<<EMBED_BLOCKS + SPLIT_BLOCKS, 256>>>(
        x, Wp, bp, Win, Wx, Wo, hh, hl, winh, winl, wxh, wxl, woh, wol);

    for (int i = 0; i < N_LAYERS; i++) {
        const bool last = (i == N_LAYERS - 1);
        // xz = h @ Win^T   (M=65536, N=512, K=128) — full tiles
        mma_gemm<false, true, false><<<dim3(M_TOT / 128, 8), 256, GEMM_SMEM>>>(
            hh, hl, winh + (size_t)i * 512 * 128, winl + (size_t)i * 512 * 128,
            xzb, nullptr, nullptr, 512, 128, 512);
        // depthwise conv + silu -> bf16 split u only
        conv_silu_kernel<<<M_TOT / CONV_ROWS, 256>>>(
            xzb, Wconv + (size_t)i * D_INNER * 4, bconv + (size_t)i * D_INNER, uh, ul);
        // dbl = u @ Wx^T   (N=40, K=256) — tail tile
        mma_gemm<false, true, true><<<dim3(M_TOT / 128, 1), 256, GEMM_SMEM>>>(
            uh, ul, wxh + (size_t)i * 40 * 256, wxl + (size_t)i * 40 * 256,
            dblb, nullptr, nullptr, 40, 256, 40);
        // chunked scan: pass A (chunks 0..6, q + telescoped P), pass C (fold prefix + emit y)
        scan_pass<false><<<dim3(128, NCH - 1), 128>>>(
            dblb, uh, ul, xzb,
            Wdt + (size_t)i * D_INNER * DT_RANK, bdt + (size_t)i * D_INNER,
            Alog + (size_t)i * D_INNER * D_STATE, Dp + (size_t)i * D_INNER,
            pqb, nullptr);
        scan_pass<true><<<dim3(128, NCH), 128>>>(
            dblb, uh, ul, xzb,
            Wdt + (size_t)i * D_INNER * DT_RANK, bdt + (size_t)i * D_INNER,
            Alog + (size_t)i * D_INNER * D_STATE, Dp + (size_t)i * D_INNER,
            nullptr, pqb);
        // h = y @ Wo^T    (N=128, K=256) — full tiles
        if (last)
            mma_gemm<false, true, false><<<dim3(M_TOT / 128, 2), 256, GEMM_SMEM>>>(
                uh, ul, woh + (size_t)i * 128 * 256, wol + (size_t)i * 128 * 256,
                h, nullptr, nullptr, 128, 256, 128);
        else
            mma_gemm<true, false, false><<<dim3(M_TOT / 128, 2), 256, GEMM_SMEM>>>(
                uh, ul, woh + (size_t)i * 128 * 256, wol + (size_t)i * 128 * 256,
                nullptr, hh, hl, 128, 256, 128);
    }

    head_kernel<<<BATCH, 512>>>(h, gln, bln, Wc, bc, out);
}